// round 1
// baseline (speedup 1.0000x reference)
#include <cuda_runtime.h>

#define N_ROWS 16384
#define DIM    256
#define NEMB   8192
#define BETA   0.25f

// Scratch (device globals — no allocation allowed)
__device__ float g_codebook[NEMB * DIM];   // 8 MB
__device__ float g_cnorm[NEMB];
__device__ int   g_idx[N_ROWS];
__device__ float g_partial[N_ROWS];

// ---------------------------------------------------------------------------
// Kernel A: codebook C[k][j] = sum_d E[k][d] * W[j][d] + b[j]
// grid (NEMB/64, DIM/64), block 256, 64x64 tile, 4x4 micro-tile
// ---------------------------------------------------------------------------
__global__ void codebook_kernel(const float* __restrict__ E,
                                const float* __restrict__ W,
                                const float* __restrict__ bias) {
    __shared__ __align__(16) float et[16][68];
    __shared__ __align__(16) float wt[16][68];
    const int tx = threadIdx.x & 15;
    const int ty = threadIdx.x >> 4;
    const int k0 = blockIdx.x * 64;
    const int j0 = blockIdx.y * 64;
    const int lr = threadIdx.x >> 2;  // 0..63
    const int lq = threadIdx.x & 3;   // 0..3

    float acc[4][4] = {};

    for (int dc = 0; dc < DIM; dc += 16) {
        float4 ev = *(const float4*)&E[(k0 + lr) * DIM + dc + lq * 4];
        float4 wv = *(const float4*)&W[(j0 + lr) * DIM + dc + lq * 4];
        et[lq * 4 + 0][lr] = ev.x; et[lq * 4 + 1][lr] = ev.y;
        et[lq * 4 + 2][lr] = ev.z; et[lq * 4 + 3][lr] = ev.w;
        wt[lq * 4 + 0][lr] = wv.x; wt[lq * 4 + 1][lr] = wv.y;
        wt[lq * 4 + 2][lr] = wv.z; wt[lq * 4 + 3][lr] = wv.w;
        __syncthreads();
        #pragma unroll
        for (int d = 0; d < 16; d++) {
            float4 a = *(const float4*)&et[d][ty * 4];
            float4 b = *(const float4*)&wt[d][tx * 4];
            acc[0][0] += a.x * b.x; acc[0][1] += a.x * b.y; acc[0][2] += a.x * b.z; acc[0][3] += a.x * b.w;
            acc[1][0] += a.y * b.x; acc[1][1] += a.y * b.y; acc[1][2] += a.y * b.z; acc[1][3] += a.y * b.w;
            acc[2][0] += a.z * b.x; acc[2][1] += a.z * b.y; acc[2][2] += a.z * b.z; acc[2][3] += a.z * b.w;
            acc[3][0] += a.w * b.x; acc[3][1] += a.w * b.y; acc[3][2] += a.w * b.z; acc[3][3] += a.w * b.w;
        }
        __syncthreads();
    }

    const float b0 = bias[j0 + tx * 4 + 0];
    const float b1 = bias[j0 + tx * 4 + 1];
    const float b2 = bias[j0 + tx * 4 + 2];
    const float b3 = bias[j0 + tx * 4 + 3];
    #pragma unroll
    for (int i = 0; i < 4; i++) {
        float4 v;
        v.x = acc[i][0] + b0; v.y = acc[i][1] + b1;
        v.z = acc[i][2] + b2; v.w = acc[i][3] + b3;
        *(float4*)&g_codebook[(k0 + ty * 4 + i) * DIM + j0 + tx * 4] = v;
    }
}

// ---------------------------------------------------------------------------
// Kernel A2: cnorm[k] = sum_j C[k][j]^2   (grid NEMB, 64 threads)
// ---------------------------------------------------------------------------
__global__ void cnorm_kernel() {
    const int k = blockIdx.x;
    const int t = threadIdx.x;
    float4 c = *(const float4*)&g_codebook[k * DIM + t * 4];
    float s = c.x * c.x + c.y * c.y + c.z * c.z + c.w * c.w;
    #pragma unroll
    for (int off = 16; off > 0; off >>= 1)
        s += __shfl_down_sync(0xffffffffu, s, off);
    __shared__ float sm[2];
    if ((t & 31) == 0) sm[t >> 5] = s;
    __syncthreads();
    if (t == 0) g_cnorm[k] = sm[0] + sm[1];
}

// ---------------------------------------------------------------------------
// Kernel B: fused distance GEMM + argmin.
// For 64 x-rows per block, loop over all 8192 codewords in 64-wide tiles.
// dist = cnorm[k] - 2 * (x . c_k). grid N_ROWS/64, block 256.
// ---------------------------------------------------------------------------
__global__ void argmin_kernel(const float* __restrict__ X) {
    __shared__ __align__(16) float xt[16][68];
    __shared__ __align__(16) float ct[16][68];
    const int tx = threadIdx.x & 15;
    const int ty = threadIdx.x >> 4;
    const int n0 = blockIdx.x * 64;
    const int lr = threadIdx.x >> 2;
    const int lq = threadIdx.x & 3;

    float bestv[4] = {1e30f, 1e30f, 1e30f, 1e30f};
    int   besti[4] = {0, 0, 0, 0};

    for (int kt = 0; kt < NEMB; kt += 64) {
        float acc[4][4] = {};
        for (int dc = 0; dc < DIM; dc += 16) {
            float4 xv = *(const float4*)&X[(n0 + lr) * DIM + dc + lq * 4];
            float4 cv = *(const float4*)&g_codebook[(kt + lr) * DIM + dc + lq * 4];
            xt[lq * 4 + 0][lr] = xv.x; xt[lq * 4 + 1][lr] = xv.y;
            xt[lq * 4 + 2][lr] = xv.z; xt[lq * 4 + 3][lr] = xv.w;
            ct[lq * 4 + 0][lr] = cv.x; ct[lq * 4 + 1][lr] = cv.y;
            ct[lq * 4 + 2][lr] = cv.z; ct[lq * 4 + 3][lr] = cv.w;
            __syncthreads();
            #pragma unroll
            for (int d = 0; d < 16; d++) {
                float4 a = *(const float4*)&xt[d][ty * 4];
                float4 b = *(const float4*)&ct[d][tx * 4];
                acc[0][0] += a.x * b.x; acc[0][1] += a.x * b.y; acc[0][2] += a.x * b.z; acc[0][3] += a.x * b.w;
                acc[1][0] += a.y * b.x; acc[1][1] += a.y * b.y; acc[1][2] += a.y * b.z; acc[1][3] += a.y * b.w;
                acc[2][0] += a.z * b.x; acc[2][1] += a.z * b.y; acc[2][2] += a.z * b.z; acc[2][3] += a.z * b.w;
                acc[3][0] += a.w * b.x; acc[3][1] += a.w * b.y; acc[3][2] += a.w * b.z; acc[3][3] += a.w * b.w;
            }
            __syncthreads();
        }
        // epilogue: dist + running argmin (j ascending, kt ascending, strict <
        // => lowest index kept on ties, matching jnp.argmin)
        #pragma unroll
        for (int j = 0; j < 4; j++) {
            const int kg = kt + tx * 4 + j;
            const float cn = g_cnorm[kg];
            #pragma unroll
            for (int i = 0; i < 4; i++) {
                float dist = cn - 2.0f * acc[i][j];
                if (dist < bestv[i]) { bestv[i] = dist; besti[i] = kg; }
            }
        }
    }

    // cross-thread reduce per row (16 candidates per row)
    __shared__ float rv[64][17];
    __shared__ int   ri[64][17];
    #pragma unroll
    for (int i = 0; i < 4; i++) {
        rv[ty * 4 + i][tx] = bestv[i];
        ri[ty * 4 + i][tx] = besti[i];
    }
    __syncthreads();
    if (threadIdx.x < 64) {
        const int row = threadIdx.x;
        float bv = rv[row][0];
        int   bi = ri[row][0];
        #pragma unroll
        for (int t = 1; t < 16; t++) {
            float v = rv[row][t];
            int   ii = ri[row][t];
            if (v < bv || (v == bv && ii < bi)) { bv = v; bi = ii; }
        }
        g_idx[n0 + row] = bi;
    }
}

// ---------------------------------------------------------------------------
// Kernel C: gather z_q = C[idx], write z_q and indices, per-row squared-diff
// partial. grid N_ROWS, 64 threads.
// ---------------------------------------------------------------------------
__global__ void gather_kernel(const float* __restrict__ X,
                              float* __restrict__ out, int out_size) {
    const int n = blockIdx.x;
    const int t = threadIdx.x;
    const int idx = g_idx[n];
    float4 c = *(const float4*)&g_codebook[idx * DIM + t * 4];
    float4 x = *(const float4*)&X[n * DIM + t * 4];
    if (n * DIM + t * 4 + 3 < out_size)
        *(float4*)&out[n * DIM + t * 4] = c;
    float dx = c.x - x.x, dy = c.y - x.y, dz = c.z - x.z, dw = c.w - x.w;
    float s = dx * dx + dy * dy + dz * dz + dw * dw;
    #pragma unroll
    for (int off = 16; off > 0; off >>= 1)
        s += __shfl_down_sync(0xffffffffu, s, off);
    __shared__ float sm[2];
    if ((t & 31) == 0) sm[t >> 5] = s;
    __syncthreads();
    if (t == 0) {
        g_partial[n] = sm[0] + sm[1];
        const int p = N_ROWS * DIM + 1 + n;
        if (p < out_size) out[p] = (float)idx;
    }
}

// ---------------------------------------------------------------------------
// Kernel D: deterministic reduction of partials -> diff scalar
// ---------------------------------------------------------------------------
__global__ void finalize_kernel(float* __restrict__ out, int out_size) {
    __shared__ float sm[1024];
    const int t = threadIdx.x;
    float s = 0.0f;
    for (int i = t; i < N_ROWS; i += 1024) s += g_partial[i];
    sm[t] = s;
    __syncthreads();
    for (int off = 512; off > 0; off >>= 1) {
        if (t < off) sm[t] += sm[t + off];
        __syncthreads();
    }
    if (t == 0) {
        const int p = N_ROWS * DIM;
        if (p < out_size)
            out[p] = sm[0] * (1.0f + BETA) / (float)(N_ROWS * DIM);
    }
}

// ---------------------------------------------------------------------------
extern "C" void kernel_launch(void* const* d_in, const int* in_sizes, int n_in,
                              void* d_out, int out_size) {
    const float* X = (const float*)d_in[0];   // [16,1024,256]
    const float* E = (const float*)d_in[1];   // [8192,256]
    const float* W = (const float*)d_in[2];   // [256,256]
    const float* b = (const float*)d_in[3];   // [256]
    float* out = (float*)d_out;

    codebook_kernel<<<dim3(NEMB / 64, DIM / 64), 256>>>(E, W, b);
    cnorm_kernel<<<NEMB, 64>>>();
    argmin_kernel<<<N_ROWS / 64, 256>>>(X);
    gather_kernel<<<N_ROWS, 64>>>(X, out, out_size);
    finalize_kernel<<<1, 1024>>>(out, out_size);
}

// round 3
// speedup vs baseline: 3.8134x; 3.8134x over previous
#include <cuda_runtime.h>
#include <cuda_fp16.h>
#include <cstdint>

#define N_ROWS 16384
#define DIM    256
#define NEMB   8192
#define BETA   0.25f

// Scaling: x*32, c*256 -> acc = 8192 * (x.c);  dist = cnorm - acc * (2/8192)
#define INV2SCALE 0.000244140625f   // 2/8192

// ------------------------- device scratch (no allocs) ----------------------
__device__ float  g_codebook[NEMB * DIM];   // exact fp32 projected codebook
__device__ float  g_cnorm[NEMB];
__device__ __half g_chi[NEMB * DIM];
__device__ __half g_clo[NEMB * DIM];
__device__ __half g_xhi[N_ROWS * DIM];
__device__ __half g_xlo[N_ROWS * DIM];
__device__ int    g_idx[N_ROWS];
__device__ float  g_partial[N_ROWS];

// ------------------------- smem layout for argmin_mma ----------------------
// X slab: 128 rows x 264 halfs (256 data + 8 pad) x 2B  = 67584 B per split
#define XS_BYTES      67584
#define XS_ROW_BYTES  528          // 264 halfs
#define SMEM_CB       135168       // 2 bufs x 2 splits x (128 x 72 halfs)
#define CB_BUF_BYTES  36864
#define CB_SPLIT_B    18432
#define CB_ROW_BYTES  144          // 72 halfs (64 data + 8 pad)
#define SMEM_RED      208896
#define SMEM_TOTAL_B  217088

__device__ __forceinline__ void cp16(unsigned dst, const void* src) {
    asm volatile("cp.async.cg.shared.global [%0], [%1], 16;"
                 :: "r"(dst), "l"(src) : "memory");
}

#define MMA16816(d, a, b0, b1)                                              \
    asm volatile("mma.sync.aligned.m16n8k16.row.col.f32.f16.f16.f32 "       \
                 "{%0,%1,%2,%3}, {%4,%5,%6,%7}, {%8,%9}, {%0,%1,%2,%3};"    \
                 : "+f"(d[0]), "+f"(d[1]), "+f"(d[2]), "+f"(d[3])           \
                 : "r"(a[0]), "r"(a[1]), "r"(a[2]), "r"(a[3]),              \
                   "r"(b0), "r"(b1))

// ---------------------------------------------------------------------------
// Kernel A: codebook C[k][j] = sum_d E[k][d] * W[j][d] + b[j]   (exact fp32)
// ---------------------------------------------------------------------------
__global__ void codebook_kernel(const float* __restrict__ E,
                                const float* __restrict__ W,
                                const float* __restrict__ bias) {
    __shared__ __align__(16) float et[16][68];
    __shared__ __align__(16) float wt[16][68];
    const int tx = threadIdx.x & 15;
    const int ty = threadIdx.x >> 4;
    const int k0 = blockIdx.x * 64;
    const int j0 = blockIdx.y * 64;
    const int lr = threadIdx.x >> 2;
    const int lq = threadIdx.x & 3;

    float acc[4][4] = {};
    for (int dc = 0; dc < DIM; dc += 16) {
        float4 ev = *(const float4*)&E[(k0 + lr) * DIM + dc + lq * 4];
        float4 wv = *(const float4*)&W[(j0 + lr) * DIM + dc + lq * 4];
        et[lq * 4 + 0][lr] = ev.x; et[lq * 4 + 1][lr] = ev.y;
        et[lq * 4 + 2][lr] = ev.z; et[lq * 4 + 3][lr] = ev.w;
        wt[lq * 4 + 0][lr] = wv.x; wt[lq * 4 + 1][lr] = wv.y;
        wt[lq * 4 + 2][lr] = wv.z; wt[lq * 4 + 3][lr] = wv.w;
        __syncthreads();
        #pragma unroll
        for (int d = 0; d < 16; d++) {
            float4 a = *(const float4*)&et[d][ty * 4];
            float4 b = *(const float4*)&wt[d][tx * 4];
            acc[0][0] += a.x * b.x; acc[0][1] += a.x * b.y; acc[0][2] += a.x * b.z; acc[0][3] += a.x * b.w;
            acc[1][0] += a.y * b.x; acc[1][1] += a.y * b.y; acc[1][2] += a.y * b.z; acc[1][3] += a.y * b.w;
            acc[2][0] += a.z * b.x; acc[2][1] += a.z * b.y; acc[2][2] += a.z * b.z; acc[2][3] += a.z * b.w;
            acc[3][0] += a.w * b.x; acc[3][1] += a.w * b.y; acc[3][2] += a.w * b.z; acc[3][3] += a.w * b.w;
        }
        __syncthreads();
    }
    const float b0 = bias[j0 + tx * 4 + 0];
    const float b1 = bias[j0 + tx * 4 + 1];
    const float b2 = bias[j0 + tx * 4 + 2];
    const float b3 = bias[j0 + tx * 4 + 3];
    #pragma unroll
    for (int i = 0; i < 4; i++) {
        float4 v;
        v.x = acc[i][0] + b0; v.y = acc[i][1] + b1;
        v.z = acc[i][2] + b2; v.w = acc[i][3] + b3;
        *(float4*)&g_codebook[(k0 + ty * 4 + i) * DIM + j0 + tx * 4] = v;
    }
}

// ---------------------------------------------------------------------------
__global__ void cnorm_kernel() {
    const int k = blockIdx.x;
    const int t = threadIdx.x;
    float4 c = *(const float4*)&g_codebook[k * DIM + t * 4];
    float s = c.x * c.x + c.y * c.y + c.z * c.z + c.w * c.w;
    #pragma unroll
    for (int off = 16; off > 0; off >>= 1)
        s += __shfl_down_sync(0xffffffffu, s, off);
    __shared__ float sm[2];
    if ((t & 31) == 0) sm[t >> 5] = s;
    __syncthreads();
    if (t == 0) g_cnorm[k] = sm[0] + sm[1];
}

// ---------------------------------------------------------------------------
// Split kernels: v -> (hi, lo) fp16 pair (scaled for normal-range residuals)
// ---------------------------------------------------------------------------
__global__ void splitX_kernel(const float* __restrict__ X) {
    const int i = blockIdx.x * 256 + threadIdx.x;
    float v = X[i] * 32.0f;
    __half h = __float2half_rn(v);
    g_xhi[i] = h;
    g_xlo[i] = __float2half_rn(v - __half2float(h));
}

__global__ void splitC_kernel() {
    const int i = blockIdx.x * 256 + threadIdx.x;
    float v = g_codebook[i] * 256.0f;
    __half h = __float2half_rn(v);
    g_chi[i] = h;
    g_clo[i] = __float2half_rn(v - __half2float(h));
}

// ---------------------------------------------------------------------------
// Kernel B: tensor-core distance GEMM + fused argmin.
// 128 blocks x 256 threads. Block tile M=128 (X rows resident in smem as
// fp16 hi/lo), loop over 64 codebook tiles of N=128, K staged in 64-chunks
// via double-buffered cp.async. Warps 4(m) x 2(n), warp tile 32x64.
// 3-term split-fp16 mma => fp32-grade dot products.
// ---------------------------------------------------------------------------
extern __shared__ char smem_raw[];

__device__ __forceinline__ void prefetch_c(int st, unsigned sbase, int tid) {
    const int nt = st >> 2;
    const int ks = st & 3;
    const unsigned dbase = sbase + SMEM_CB + (unsigned)(st & 1) * CB_BUF_BYTES;
    #pragma unroll
    for (int s = 0; s < 2; s++) {
        const __half* src = (s ? g_clo : g_chi) + (nt * 128) * DIM + ks * 64;
        const unsigned db = dbase + s * CB_SPLIT_B;
        #pragma unroll
        for (int i = 0; i < 4; i++) {
            int seg = tid + i * 256;        // 0..1023
            int row = seg >> 3, part = seg & 7;
            cp16(db + row * CB_ROW_BYTES + part * 16, src + row * DIM + part * 8);
        }
    }
    asm volatile("cp.async.commit_group;" ::: "memory");
}

__global__ void __launch_bounds__(256, 1) argmin_mma_kernel() {
    const int tid = threadIdx.x;
    const int m0 = blockIdx.x * 128;
    const unsigned sbase = (unsigned)__cvta_generic_to_shared(smem_raw);

    // ---- prologue: stage X slab (hi/lo) + C stage 0, one cp.async group ----
    #pragma unroll
    for (int s = 0; s < 2; s++) {
        const __half* src = s ? g_xlo : g_xhi;
        const unsigned db = sbase + s * XS_BYTES;
        #pragma unroll
        for (int i = 0; i < 16; i++) {
            int seg = tid + i * 256;        // 0..4095
            int row = seg >> 5, part = seg & 31;
            cp16(db + row * XS_ROW_BYTES + part * 16,
                 src + (m0 + row) * DIM + part * 8);
        }
    }
    prefetch_c(0, sbase, tid);

    const int lane = tid & 31;
    const int wid  = tid >> 5;
    const int wy   = wid & 3;       // m warp (0..3)
    const int wx   = wid >> 2;      // n warp (0..1)
    const int gid  = lane >> 2;     // 0..7
    const int tq   = lane & 3;      // 0..3

    const unsigned* xshi = (const unsigned*)smem_raw;   // stride 132 u32/row
    const unsigned* xslo = (const unsigned*)(smem_raw + XS_BYTES);

    float bestv[4] = {3.4e38f, 3.4e38f, 3.4e38f, 3.4e38f};
    int   besti[4] = {0, 0, 0, 0};
    float acc[2][8][4];
    #pragma unroll
    for (int a = 0; a < 2; a++)
        #pragma unroll
        for (int b = 0; b < 8; b++)
            #pragma unroll
            for (int c = 0; c < 4; c++) acc[a][b][c] = 0.0f;

    const int abase0 = (wy * 32 + gid) * 132 + tq;       // msub 0
    const int abase1 = abase0 + 16 * 132;                // msub 1
    const int bbase  = (wx * 64 + gid) * 36 + tq;        // per n-frag: +nf*8*36

    for (int st = 0; st < 256; st++) {
        asm volatile("cp.async.wait_group 0;" ::: "memory");
        __syncthreads();
        if (st + 1 < 256) prefetch_c(st + 1, sbase, tid);

        const unsigned* cbhi = (const unsigned*)(smem_raw + SMEM_CB + (st & 1) * CB_BUF_BYTES);
        const unsigned* cblo = cbhi + CB_SPLIT_B / 4;

        #pragma unroll
        for (int kk = 0; kk < 4; kk++) {
            const int ko = (st & 3) * 32 + kk * 8;   // u32 offset into X row
            unsigned ahi[2][4];
            unsigned alo[2][4];
            #pragma unroll
            for (int ms = 0; ms < 2; ms++) {
                const int ra = (ms ? abase1 : abase0) + ko;
                ahi[ms][0] = xshi[ra];            ahi[ms][1] = xshi[ra + 8 * 132];
                ahi[ms][2] = xshi[ra + 4];        ahi[ms][3] = xshi[ra + 8 * 132 + 4];
                alo[ms][0] = xslo[ra];            alo[ms][1] = xslo[ra + 8 * 132];
                alo[ms][2] = xslo[ra + 4];        alo[ms][3] = xslo[ra + 8 * 132 + 4];
            }
            #pragma unroll
            for (int nf = 0; nf < 8; nf++) {
                const int rb = bbase + nf * 8 * 36 + kk * 8;
                const unsigned bh0 = cbhi[rb];
                const unsigned bh1 = cbhi[rb + 4];
                const unsigned bl0 = cblo[rb];
                const unsigned bl1 = cblo[rb + 4];
                #pragma unroll
                for (int ms = 0; ms < 2; ms++) {
                    MMA16816(acc[ms][nf], ahi[ms], bh0, bh1);
                    MMA16816(acc[ms][nf], ahi[ms], bl0, bl1);
                    MMA16816(acc[ms][nf], alo[ms], bh0, bh1);
                }
            }
        }

        if ((st & 3) == 3) {
            const int nt = st >> 2;
            #pragma unroll
            for (int nf = 0; nf < 8; nf++) {
                const int col = nt * 128 + wx * 64 + nf * 8 + tq * 2;
                const float cn0 = __ldg(&g_cnorm[col]);
                const float cn1 = __ldg(&g_cnorm[col + 1]);
                #pragma unroll
                for (int ms = 0; ms < 2; ms++) {
                    const int s0 = ms * 2, s1 = ms * 2 + 1;
                    float d0 = cn0 - acc[ms][nf][0] * INV2SCALE;   // row gid,   col
                    float d1 = cn1 - acc[ms][nf][1] * INV2SCALE;   // row gid,   col+1
                    float d2 = cn0 - acc[ms][nf][2] * INV2SCALE;   // row gid+8, col
                    float d3 = cn1 - acc[ms][nf][3] * INV2SCALE;   // row gid+8, col+1
                    if (d0 < bestv[s0]) { bestv[s0] = d0; besti[s0] = col; }
                    if (d1 < bestv[s0]) { bestv[s0] = d1; besti[s0] = col + 1; }
                    if (d2 < bestv[s1]) { bestv[s1] = d2; besti[s1] = col; }
                    if (d3 < bestv[s1]) { bestv[s1] = d3; besti[s1] = col + 1; }
                    acc[ms][nf][0] = 0.0f; acc[ms][nf][1] = 0.0f;
                    acc[ms][nf][2] = 0.0f; acc[ms][nf][3] = 0.0f;
                }
            }
        }
    }

    // ---- cross-thread reduce: 8 candidates per row ----
    float* rv = (float*)(smem_raw + SMEM_RED);
    int*   ri = (int*)(smem_raw + SMEM_RED + 4096);
    __syncthreads();
    #pragma unroll
    for (int s = 0; s < 4; s++) {
        // slot s covers row wy*32 + (s&1)*8 + gid for msub s>>1
        const int row = wy * 32 + (s >> 1) * 16 + (s & 1) * 8 + gid;
        rv[row * 8 + wx * 4 + tq] = bestv[s];
        ri[row * 8 + wx * 4 + tq] = besti[s];
    }
    __syncthreads();
    if (tid < 128) {
        float bv = rv[tid * 8];
        int   bi = ri[tid * 8];
        #pragma unroll
        for (int j = 1; j < 8; j++) {
            float v = rv[tid * 8 + j];
            int  ii = ri[tid * 8 + j];
            if (v < bv || (v == bv && ii < bi)) { bv = v; bi = ii; }
        }
        g_idx[m0 + tid] = bi;
    }
}

// ---------------------------------------------------------------------------
// Kernel C: gather z_q = C[idx] (exact fp32), write outputs + loss partials
// ---------------------------------------------------------------------------
__global__ void gather_kernel(const float* __restrict__ X,
                              float* __restrict__ out, int out_size) {
    const int n = blockIdx.x;
    const int t = threadIdx.x;
    const int idx = g_idx[n];
    float4 c = *(const float4*)&g_codebook[idx * DIM + t * 4];
    float4 x = *(const float4*)&X[n * DIM + t * 4];
    if (n * DIM + t * 4 + 3 < out_size)
        *(float4*)&out[n * DIM + t * 4] = c;
    float dx = c.x - x.x, dy = c.y - x.y, dz = c.z - x.z, dw = c.w - x.w;
    float s = dx * dx + dy * dy + dz * dz + dw * dw;
    #pragma unroll
    for (int off = 16; off > 0; off >>= 1)
        s += __shfl_down_sync(0xffffffffu, s, off);
    __shared__ float sm[2];
    if ((t & 31) == 0) sm[t >> 5] = s;
    __syncthreads();
    if (t == 0) {
        g_partial[n] = sm[0] + sm[1];
        const int p = N_ROWS * DIM + 1 + n;
        if (p < out_size) out[p] = (float)idx;
    }
}

__global__ void finalize_kernel(float* __restrict__ out, int out_size) {
    __shared__ float sm[1024];
    const int t = threadIdx.x;
    float s = 0.0f;
    for (int i = t; i < N_ROWS; i += 1024) s += g_partial[i];
    sm[t] = s;
    __syncthreads();
    for (int off = 512; off > 0; off >>= 1) {
        if (t < off) sm[t] += sm[t + off];
        __syncthreads();
    }
    if (t == 0) {
        const int p = N_ROWS * DIM;
        if (p < out_size)
            out[p] = sm[0] * (1.0f + BETA) / (float)(N_ROWS * DIM);
    }
}

// ---------------------------------------------------------------------------
extern "C" void kernel_launch(void* const* d_in, const int* in_sizes, int n_in,
                              void* d_out, int out_size) {
    const float* X = (const float*)d_in[0];
    const float* E = (const float*)d_in[1];
    const float* W = (const float*)d_in[2];
    const float* b = (const float*)d_in[3];
    float* out = (float*)d_out;

    cudaFuncSetAttribute(argmin_mma_kernel,
                         cudaFuncAttributeMaxDynamicSharedMemorySize,
                         SMEM_TOTAL_B);

    codebook_kernel<<<dim3(NEMB / 64, DIM / 64), 256>>>(E, W, b);
    cnorm_kernel<<<NEMB, 64>>>();
    splitC_kernel<<<NEMB * DIM / 256, 256>>>();
    splitX_kernel<<<N_ROWS * DIM / 256, 256>>>(X);
    argmin_mma_kernel<<<N_ROWS / 128, 256, SMEM_TOTAL_B>>>();
    gather_kernel<<<N_ROWS, 64>>>(X, out, out_size);
    finalize_kernel<<<1, 1024>>>(out, out_size);
}

// round 5
// speedup vs baseline: 3.9132x; 1.0262x over previous
#include <cuda_runtime.h>
#include <cuda_fp16.h>
#include <cstdint>

#define N_ROWS 16384
#define DIM    256
#define NEMB   8192
#define BETA   0.25f
#define INV2SCALE 0.000244140625f   // 2/8192 ; acc = 8192*(x.c)

// ------------------------- device scratch (no allocs) ----------------------
__device__ float  g_codebook[NEMB * DIM];
__device__ float  g_cnorm[NEMB];
__device__ __half g_chi[NEMB * DIM];
__device__ __half g_clo[NEMB * DIM];
__device__ int    g_idx[N_ROWS];
__device__ float  g_partial[N_ROWS];

// ------------------------- smem layout for argmin_mma ----------------------
#define XHI           0            // 128 rows x 264 halfs (8-half pad) = 67584B
#define XLO           67584
#define XS_ROW_BYTES  528
#define SMEM_CB       135168       // 2 bufs x 2 splits x (128 x 72 halfs)
#define CB_BUF_BYTES  36864
#define CB_SPLIT_B    18432
#define CB_ROW_BYTES  144
#define SMEM_RED      208896
#define SMEM_TOTAL_B  217088

__device__ __forceinline__ void cp16(unsigned dst, const void* src) {
    asm volatile("cp.async.cg.shared.global [%0], [%1], 16;"
                 :: "r"(dst), "l"(src) : "memory");
}

#define MMA16816(d, a, b0, b1)                                              \
    asm volatile("mma.sync.aligned.m16n8k16.row.col.f32.f16.f16.f32 "       \
                 "{%0,%1,%2,%3}, {%4,%5,%6,%7}, {%8,%9}, {%0,%1,%2,%3};"    \
                 : "+f"(d[0]), "+f"(d[1]), "+f"(d[2]), "+f"(d[3])           \
                 : "r"(a[0]), "r"(a[1]), "r"(a[2]), "r"(a[3]),              \
                   "r"(b0), "r"(b1))

#define LDSM_X4(r0, r1, r2, r3, addr)                                       \
    asm volatile("ldmatrix.sync.aligned.m8n8.x4.shared.b16 "                \
                 "{%0,%1,%2,%3}, [%4];"                                     \
                 : "=r"(r0), "=r"(r1), "=r"(r2), "=r"(r3) : "r"(addr))

// (a,b) -> packed fp16 hi pair; residual lo pair in *lo
__device__ __forceinline__ unsigned split2(float a, float b, unsigned* lo) {
    __half ha = __float2half_rn(a), hb = __float2half_rn(b);
    __half la = __float2half_rn(a - __half2float(ha));
    __half lb = __float2half_rn(b - __half2float(hb));
    *lo = ((unsigned)__half_as_ushort(lb) << 16) | __half_as_ushort(la);
    return ((unsigned)__half_as_ushort(hb) << 16) | __half_as_ushort(ha);
}

// ---------------------------------------------------------------------------
// Kernel A: codebook C[k][j] = sum_d E[k][d]*W[j][d] + b[j]  (exact fp32)
// epilogue also emits the scaled split-fp16 codebook (g_chi/g_clo).
// ---------------------------------------------------------------------------
__global__ void codebook_kernel(const float* __restrict__ E,
                                const float* __restrict__ W,
                                const float* __restrict__ bias) {
    __shared__ __align__(16) float et[16][68];
    __shared__ __align__(16) float wt[16][68];
    const int tx = threadIdx.x & 15;
    const int ty = threadIdx.x >> 4;
    const int k0 = blockIdx.x * 64;
    const int j0 = blockIdx.y * 64;
    const int lr = threadIdx.x >> 2;
    const int lq = threadIdx.x & 3;

    float acc[4][4] = {};
    for (int dc = 0; dc < DIM; dc += 16) {
        float4 ev = *(const float4*)&E[(k0 + lr) * DIM + dc + lq * 4];
        float4 wv = *(const float4*)&W[(j0 + lr) * DIM + dc + lq * 4];
        et[lq * 4 + 0][lr] = ev.x; et[lq * 4 + 1][lr] = ev.y;
        et[lq * 4 + 2][lr] = ev.z; et[lq * 4 + 3][lr] = ev.w;
        wt[lq * 4 + 0][lr] = wv.x; wt[lq * 4 + 1][lr] = wv.y;
        wt[lq * 4 + 2][lr] = wv.z; wt[lq * 4 + 3][lr] = wv.w;
        __syncthreads();
        #pragma unroll
        for (int d = 0; d < 16; d++) {
            float4 a = *(const float4*)&et[d][ty * 4];
            float4 b = *(const float4*)&wt[d][tx * 4];
            acc[0][0] += a.x * b.x; acc[0][1] += a.x * b.y; acc[0][2] += a.x * b.z; acc[0][3] += a.x * b.w;
            acc[1][0] += a.y * b.x; acc[1][1] += a.y * b.y; acc[1][2] += a.y * b.z; acc[1][3] += a.y * b.w;
            acc[2][0] += a.z * b.x; acc[2][1] += a.z * b.y; acc[2][2] += a.z * b.z; acc[2][3] += a.z * b.w;
            acc[3][0] += a.w * b.x; acc[3][1] += a.w * b.y; acc[3][2] += a.w * b.z; acc[3][3] += a.w * b.w;
        }
        __syncthreads();
    }
    const float b0 = bias[j0 + tx * 4 + 0];
    const float b1 = bias[j0 + tx * 4 + 1];
    const float b2 = bias[j0 + tx * 4 + 2];
    const float b3 = bias[j0 + tx * 4 + 3];
    #pragma unroll
    for (int i = 0; i < 4; i++) {
        float4 v;
        v.x = acc[i][0] + b0; v.y = acc[i][1] + b1;
        v.z = acc[i][2] + b2; v.w = acc[i][3] + b3;
        const int k = k0 + ty * 4 + i;
        const int j = j0 + tx * 4;
        *(float4*)&g_codebook[k * DIM + j] = v;
        unsigned lo01, lo23;
        unsigned hi01 = split2(v.x * 256.0f, v.y * 256.0f, &lo01);
        unsigned hi23 = split2(v.z * 256.0f, v.w * 256.0f, &lo23);
        *(uint2*)&g_chi[k * DIM + j] = make_uint2(hi01, hi23);
        *(uint2*)&g_clo[k * DIM + j] = make_uint2(lo01, lo23);
    }
}

// ---------------------------------------------------------------------------
__global__ void cnorm_kernel() {
    const int k = blockIdx.x;
    const int t = threadIdx.x;
    float4 c = *(const float4*)&g_codebook[k * DIM + t * 4];
    float s = c.x * c.x + c.y * c.y + c.z * c.z + c.w * c.w;
    #pragma unroll
    for (int off = 16; off > 0; off >>= 1)
        s += __shfl_down_sync(0xffffffffu, s, off);
    __shared__ float sm[2];
    if ((t & 31) == 0) sm[t >> 5] = s;
    __syncthreads();
    if (t == 0) g_cnorm[k] = sm[0] + sm[1];
}

// ---------------------------------------------------------------------------
// Kernel B: split-fp16 mma.sync distance GEMM + fused argmin, LDSM fragments.
// 128 blocks x 256 threads; M=128 X rows split in-kernel into smem hi/lo,
// N-tiles of 128, K staged in 64s via double-buffered cp.async.
// ---------------------------------------------------------------------------
extern __shared__ char smem_raw[];

__device__ __forceinline__ void prefetch_c(int st, unsigned sbase, int tid) {
    const int nt = st >> 2;
    const int ks = st & 3;
    const unsigned dbase = sbase + SMEM_CB + (unsigned)(st & 1) * CB_BUF_BYTES;
    #pragma unroll
    for (int s = 0; s < 2; s++) {
        const __half* src = (s ? g_clo : g_chi) + (nt * 128) * DIM + ks * 64;
        const unsigned db = dbase + s * CB_SPLIT_B;
        #pragma unroll
        for (int i = 0; i < 4; i++) {
            int seg = tid + i * 256;        // 0..1023
            int row = seg >> 3, part = seg & 7;
            cp16(db + row * CB_ROW_BYTES + part * 16, src + row * DIM + part * 8);
        }
    }
    asm volatile("cp.async.commit_group;" ::: "memory");
}

__global__ void __launch_bounds__(256, 1) argmin_mma_kernel(const float* __restrict__ X) {
    const int tid = threadIdx.x;
    const int m0 = blockIdx.x * 128;
    const unsigned sb = (unsigned)__cvta_generic_to_shared(smem_raw);

    prefetch_c(0, sb, tid);

    // ---- prologue: read X fp32, split to fp16 hi/lo directly in smem ----
    {
        unsigned* xh = (unsigned*)smem_raw;             // row stride 132 u32
        unsigned* xl = (unsigned*)(smem_raw + XLO);
        #pragma unroll
        for (int i = 0; i < 32; i++) {
            int seg = tid + i * 256;        // 0..8191
            int row = seg >> 6, c4 = seg & 63;
            float4 xv = *(const float4*)&X[(m0 + row) * DIM + c4 * 4];
            unsigned lo01, lo23;
            unsigned hi01 = split2(xv.x * 32.0f, xv.y * 32.0f, &lo01);
            unsigned hi23 = split2(xv.z * 32.0f, xv.w * 32.0f, &lo23);
            xh[row * 132 + c4 * 2]     = hi01;
            xh[row * 132 + c4 * 2 + 1] = hi23;
            xl[row * 132 + c4 * 2]     = lo01;
            xl[row * 132 + c4 * 2 + 1] = lo23;
        }
    }

    const int lane = tid & 31;
    const int wid  = tid >> 5;
    const int wy   = wid & 3;       // m warp (0..3)
    const int wx   = wid >> 2;      // n warp (0..1)
    const int gid  = lane >> 2;     // 0..7
    const int tq   = lane & 3;      // 0..3

    // LDSM per-lane bases
    const int arow = wy * 32 + (lane & 7) + ((lane >> 3) & 1) * 8;
    const unsigned a_hi0 = sb + XHI + (unsigned)arow * XS_ROW_BYTES + (unsigned)((lane >> 4) * 16);
    const unsigned a_hi1 = a_hi0 + 16u * XS_ROW_BYTES;
    const unsigned a_lo0 = a_hi0 + (XLO - XHI);
    const unsigned a_lo1 = a_lo0 + 16u * XS_ROW_BYTES;
    const int brow = wx * 64 + (lane & 7) + ((lane >> 4) & 1) * 8;
    const unsigned b_off = (unsigned)brow * CB_ROW_BYTES + (unsigned)(((lane >> 3) & 1) * 16);

    float bestv[4] = {3.4e38f, 3.4e38f, 3.4e38f, 3.4e38f};
    int   besti[4] = {0, 0, 0, 0};
    float acc[2][8][4];
    #pragma unroll
    for (int a = 0; a < 2; a++)
        #pragma unroll
        for (int b = 0; b < 8; b++)
            #pragma unroll
            for (int c = 0; c < 4; c++) acc[a][b][c] = 0.0f;

    for (int st = 0; st < 256; st++) {
        asm volatile("cp.async.wait_group 0;" ::: "memory");
        __syncthreads();
        if (st + 1 < 256) prefetch_c(st + 1, sb, tid);

        const unsigned bh_base = sb + SMEM_CB + (unsigned)(st & 1) * CB_BUF_BYTES + b_off;
        const unsigned bl_base = bh_base + CB_SPLIT_B;

        #pragma unroll
        for (int kk = 0; kk < 4; kk++) {
            const unsigned aoff = (unsigned)(((st & 3) * 64 + kk * 16) * 2);
            unsigned ahi[2][4], alo[2][4];
            LDSM_X4(ahi[0][0], ahi[0][1], ahi[0][2], ahi[0][3], a_hi0 + aoff);
            LDSM_X4(ahi[1][0], ahi[1][1], ahi[1][2], ahi[1][3], a_hi1 + aoff);
            LDSM_X4(alo[0][0], alo[0][1], alo[0][2], alo[0][3], a_lo0 + aoff);
            LDSM_X4(alo[1][0], alo[1][1], alo[1][2], alo[1][3], a_lo1 + aoff);
            #pragma unroll
            for (int p = 0; p < 4; p++) {
                unsigned bh0, bh1, bh2, bh3, bl0, bl1, bl2, bl3;
                LDSM_X4(bh0, bh1, bh2, bh3, bh_base + p * 2304u + kk * 32u);
                LDSM_X4(bl0, bl1, bl2, bl3, bl_base + p * 2304u + kk * 32u);
                #pragma unroll
                for (int ms = 0; ms < 2; ms++) {
                    MMA16816(acc[ms][2 * p],     ahi[ms], bh0, bh1);
                    MMA16816(acc[ms][2 * p],     ahi[ms], bl0, bl1);
                    MMA16816(acc[ms][2 * p],     alo[ms], bh0, bh1);
                    MMA16816(acc[ms][2 * p + 1], ahi[ms], bh2, bh3);
                    MMA16816(acc[ms][2 * p + 1], ahi[ms], bl2, bl3);
                    MMA16816(acc[ms][2 * p + 1], alo[ms], bh2, bh3);
                }
            }
        }

        if ((st & 3) == 3) {
            const int nt = st >> 2;
            #pragma unroll
            for (int nf = 0; nf < 8; nf++) {
                const int col = nt * 128 + wx * 64 + nf * 8 + tq * 2;
                const float cn0 = __ldg(&g_cnorm[col]);
                const float cn1 = __ldg(&g_cnorm[col + 1]);
                #pragma unroll
                for (int ms = 0; ms < 2; ms++) {
                    const int s0 = ms * 2, s1 = ms * 2 + 1;
                    float d0 = cn0 - acc[ms][nf][0] * INV2SCALE;
                    float d1 = cn1 - acc[ms][nf][1] * INV2SCALE;
                    float d2 = cn0 - acc[ms][nf][2] * INV2SCALE;
                    float d3 = cn1 - acc[ms][nf][3] * INV2SCALE;
                    if (d0 < bestv[s0]) { bestv[s0] = d0; besti[s0] = col; }
                    if (d1 < bestv[s0]) { bestv[s0] = d1; besti[s0] = col + 1; }
                    if (d2 < bestv[s1]) { bestv[s1] = d2; besti[s1] = col; }
                    if (d3 < bestv[s1]) { bestv[s1] = d3; besti[s1] = col + 1; }
                    acc[ms][nf][0] = 0.0f; acc[ms][nf][1] = 0.0f;
                    acc[ms][nf][2] = 0.0f; acc[ms][nf][3] = 0.0f;
                }
            }
        }
    }

    // ---- cross-thread reduce: 8 candidates per row ----
    float* rv = (float*)(smem_raw + SMEM_RED);
    int*   ri = (int*)(smem_raw + SMEM_RED + 4096);
    __syncthreads();
    #pragma unroll
    for (int s = 0; s < 4; s++) {
        // slot s = ms*2 + rowhalf covers row wy*32 + ms*16 + rowhalf*8 + gid
        const int row = wy * 32 + (s >> 1) * 16 + (s & 1) * 8 + gid;
        rv[row * 8 + wx * 4 + tq] = bestv[s];
        ri[row * 8 + wx * 4 + tq] = besti[s];
    }
    __syncthreads();
    if (tid < 128) {
        float bv = rv[tid * 8];
        int   bi = ri[tid * 8];
        #pragma unroll
        for (int j = 1; j < 8; j++) {
            float v = rv[tid * 8 + j];
            int  ii = ri[tid * 8 + j];
            if (v < bv || (v == bv && ii < bi)) { bv = v; bi = ii; }
        }
        g_idx[m0 + tid] = bi;
    }
}

// ---------------------------------------------------------------------------
// Kernel C: gather z_q = C[idx] (exact fp32), write outputs + loss partials
// ---------------------------------------------------------------------------
__global__ void gather_kernel(const float* __restrict__ X,
                              float* __restrict__ out, int out_size) {
    const int n = blockIdx.x;
    const int t = threadIdx.x;
    const int idx = g_idx[n];
    float4 c = *(const float4*)&g_codebook[idx * DIM + t * 4];
    float4 x = *(const float4*)&X[n * DIM + t * 4];
    if (n * DIM + t * 4 + 3 < out_size)
        *(float4*)&out[n * DIM + t * 4] = c;
    float dx = c.x - x.x, dy = c.y - x.y, dz = c.z - x.z, dw = c.w - x.w;
    float s = dx * dx + dy * dy + dz * dz + dw * dw;
    #pragma unroll
    for (int off = 16; off > 0; off >>= 1)
        s += __shfl_down_sync(0xffffffffu, s, off);
    __shared__ float sm[2];
    if ((t & 31) == 0) sm[t >> 5] = s;
    __syncthreads();
    if (t == 0) {
        g_partial[n] = sm[0] + sm[1];
        const int p = N_ROWS * DIM + 1 + n;
        if (p < out_size) out[p] = (float)idx;
    }
}

__global__ void finalize_kernel(float* __restrict__ out, int out_size) {
    __shared__ float sm[1024];
    const int t = threadIdx.x;
    float s = 0.0f;
    for (int i = t; i < N_ROWS; i += 1024) s += g_partial[i];
    sm[t] = s;
    __syncthreads();
    for (int off = 512; off > 0; off >>= 1) {
        if (t < off) sm[t] += sm[t + off];
        __syncthreads();
    }
    if (t == 0) {
        const int p = N_ROWS * DIM;
        if (p < out_size)
            out[p] = sm[0] * (1.0f + BETA) / (float)(N_ROWS * DIM);
    }
}

// ---------------------------------------------------------------------------
extern "C" void kernel_launch(void* const* d_in, const int* in_sizes, int n_in,
                              void* d_out, int out_size) {
    const float* X = (const float*)d_in[0];
    const float* E = (const float*)d_in[1];
    const float* W = (const float*)d_in[2];
    const float* b = (const float*)d_in[3];
    float* out = (float*)d_out;

    cudaFuncSetAttribute(argmin_mma_kernel,
                         cudaFuncAttributeMaxDynamicSharedMemorySize,
                         SMEM_TOTAL_B);

    codebook_kernel<<<dim3(NEMB / 64, DIM / 64), 256>>>(E, W, b);
    cnorm_kernel<<<NEMB, 64>>>();
    argmin_mma_kernel<<<N_ROWS / 128, 256, SMEM_TOTAL_B>>>(X);
    gather_kernel<<<N_ROWS, 64>>>(X, out, out_size);
    finalize_kernel<<<1, 1024>>>(out, out_size);
}

// round 6
// speedup vs baseline: 4.2431x; 1.0843x over previous
#include <cuda_runtime.h>
#include <cuda_fp16.h>
#include <cstdint>

#define N_ROWS 16384
#define DIM    256
#define NEMB   8192
#define BETA   0.25f
#define INV2SCALE 0.000244140625f   // 2/8192 ; acc = 8192*(x.c)

// ------------------------- device scratch (no allocs) ----------------------
__device__ float  g_codebook[NEMB * DIM];
__device__ float  g_cnorm[NEMB];
__device__ __half g_chi[NEMB * DIM];
__device__ __half g_clo[NEMB * DIM];
__device__ int    g_idx[N_ROWS];
__device__ float  g_partial[N_ROWS];

// ------------------------- smem layout for argmin_mma ----------------------
#define XHI           0            // 128 rows x 264 halfs (8-half pad) = 67584B
#define XLO           67584
#define XS_ROW_BYTES  528
#define SMEM_CB       135168       // 2 bufs x 2 splits x (128 x 72 halfs)
#define CB_BUF_BYTES  36864
#define CB_SPLIT_B    18432
#define CB_ROW_BYTES  144
#define SMEM_RED      208896       // rv 4096 | ri 4096 | sidx 512
#define SMEM_TOTAL_B  217600

__device__ __forceinline__ void cp16(unsigned dst, const void* src) {
    asm volatile("cp.async.cg.shared.global [%0], [%1], 16;"
                 :: "r"(dst), "l"(src) : "memory");
}

#define MMA16816(d, a, b0, b1)                                              \
    asm volatile("mma.sync.aligned.m16n8k16.row.col.f32.f16.f16.f32 "       \
                 "{%0,%1,%2,%3}, {%4,%5,%6,%7}, {%8,%9}, {%0,%1,%2,%3};"    \
                 : "+f"(d[0]), "+f"(d[1]), "+f"(d[2]), "+f"(d[3])           \
                 : "r"(a[0]), "r"(a[1]), "r"(a[2]), "r"(a[3]),              \
                   "r"(b0), "r"(b1))

#define LDSM_X4(r0, r1, r2, r3, addr)                                       \
    asm volatile("ldmatrix.sync.aligned.m8n8.x4.shared.b16 "                \
                 "{%0,%1,%2,%3}, [%4];"                                     \
                 : "=r"(r0), "=r"(r1), "=r"(r2), "=r"(r3) : "r"(addr))

#define BARG(g) asm volatile("bar.sync %0, 128;" :: "r"((g) + 1) : "memory")

// (a,b) -> packed fp16 hi pair; residual lo pair in *lo
__device__ __forceinline__ unsigned split2(float a, float b, unsigned* lo) {
    __half ha = __float2half_rn(a), hb = __float2half_rn(b);
    __half la = __float2half_rn(a - __half2float(ha));
    __half lb = __float2half_rn(b - __half2float(hb));
    *lo = ((unsigned)__half_as_ushort(lb) << 16) | __half_as_ushort(la);
    return ((unsigned)__half_as_ushort(hb) << 16) | __half_as_ushort(ha);
}

// ---------------------------------------------------------------------------
// Kernel A: codebook C[k][j] = sum_d E[k][d]*W[j][d] + b[j]  (exact fp32)
// epilogue also emits the scaled split-fp16 codebook (g_chi/g_clo).
// ---------------------------------------------------------------------------
__global__ void codebook_kernel(const float* __restrict__ E,
                                const float* __restrict__ W,
                                const float* __restrict__ bias) {
    __shared__ __align__(16) float et[16][68];
    __shared__ __align__(16) float wt[16][68];
    const int tx = threadIdx.x & 15;
    const int ty = threadIdx.x >> 4;
    const int k0 = blockIdx.x * 64;
    const int j0 = blockIdx.y * 64;
    const int lr = threadIdx.x >> 2;
    const int lq = threadIdx.x & 3;

    float acc[4][4] = {};
    for (int dc = 0; dc < DIM; dc += 16) {
        float4 ev = *(const float4*)&E[(k0 + lr) * DIM + dc + lq * 4];
        float4 wv = *(const float4*)&W[(j0 + lr) * DIM + dc + lq * 4];
        et[lq * 4 + 0][lr] = ev.x; et[lq * 4 + 1][lr] = ev.y;
        et[lq * 4 + 2][lr] = ev.z; et[lq * 4 + 3][lr] = ev.w;
        wt[lq * 4 + 0][lr] = wv.x; wt[lq * 4 + 1][lr] = wv.y;
        wt[lq * 4 + 2][lr] = wv.z; wt[lq * 4 + 3][lr] = wv.w;
        __syncthreads();
        #pragma unroll
        for (int d = 0; d < 16; d++) {
            float4 a = *(const float4*)&et[d][ty * 4];
            float4 b = *(const float4*)&wt[d][tx * 4];
            acc[0][0] += a.x * b.x; acc[0][1] += a.x * b.y; acc[0][2] += a.x * b.z; acc[0][3] += a.x * b.w;
            acc[1][0] += a.y * b.x; acc[1][1] += a.y * b.y; acc[1][2] += a.y * b.z; acc[1][3] += a.y * b.w;
            acc[2][0] += a.z * b.x; acc[2][1] += a.z * b.y; acc[2][2] += a.z * b.z; acc[2][3] += a.z * b.w;
            acc[3][0] += a.w * b.x; acc[3][1] += a.w * b.y; acc[3][2] += a.w * b.z; acc[3][3] += a.w * b.w;
        }
        __syncthreads();
    }
    const float b0 = bias[j0 + tx * 4 + 0];
    const float b1 = bias[j0 + tx * 4 + 1];
    const float b2 = bias[j0 + tx * 4 + 2];
    const float b3 = bias[j0 + tx * 4 + 3];
    #pragma unroll
    for (int i = 0; i < 4; i++) {
        float4 v;
        v.x = acc[i][0] + b0; v.y = acc[i][1] + b1;
        v.z = acc[i][2] + b2; v.w = acc[i][3] + b3;
        const int k = k0 + ty * 4 + i;
        const int j = j0 + tx * 4;
        *(float4*)&g_codebook[k * DIM + j] = v;
        unsigned lo01, lo23;
        unsigned hi01 = split2(v.x * 256.0f, v.y * 256.0f, &lo01);
        unsigned hi23 = split2(v.z * 256.0f, v.w * 256.0f, &lo23);
        *(uint2*)&g_chi[k * DIM + j] = make_uint2(hi01, hi23);
        *(uint2*)&g_clo[k * DIM + j] = make_uint2(lo01, lo23);
    }
}

// ---------------------------------------------------------------------------
__global__ void cnorm_kernel() {
    const int k = blockIdx.x;
    const int t = threadIdx.x;
    float4 c = *(const float4*)&g_codebook[k * DIM + t * 4];
    float s = c.x * c.x + c.y * c.y + c.z * c.z + c.w * c.w;
    #pragma unroll
    for (int off = 16; off > 0; off >>= 1)
        s += __shfl_down_sync(0xffffffffu, s, off);
    __shared__ float sm[2];
    if ((t & 31) == 0) sm[t >> 5] = s;
    __syncthreads();
    if (t == 0) g_cnorm[k] = sm[0] + sm[1];
}

// ---------------------------------------------------------------------------
// Kernel B: split-fp16 mma.sync distance GEMM + fused argmin + fused gather.
// 128 blocks x 256 threads. Two independent 128-thread halves: warps 0-3
// (wx=0) own B rows 0-63, warps 4-7 own rows 64-127; each half loads its own
// B rows and syncs via its own named barrier -> halves free-run vs each other.
// ---------------------------------------------------------------------------
extern __shared__ char smem_raw[];

__device__ __forceinline__ void prefetch_ch(int st, unsigned sbase, int t128, int g) {
    const int nt = st >> 2;
    const int ks = st & 3;
    const unsigned dbase = sbase + SMEM_CB + (unsigned)(st & 1) * CB_BUF_BYTES
                         + (unsigned)g * 64u * CB_ROW_BYTES;
    #pragma unroll
    for (int s = 0; s < 2; s++) {
        const __half* src = (s ? g_clo : g_chi) + (nt * 128 + g * 64) * DIM + ks * 64;
        const unsigned db = dbase + s * CB_SPLIT_B;
        #pragma unroll
        for (int i = 0; i < 4; i++) {
            int seg = t128 + i * 128;       // 0..511 : 64 rows x 8 parts
            int row = seg >> 3, part = seg & 7;
            cp16(db + row * CB_ROW_BYTES + part * 16, src + row * DIM + part * 8);
        }
    }
    asm volatile("cp.async.commit_group;" ::: "memory");
}

__global__ void __launch_bounds__(256, 1) argmin_mma_kernel(
        const float* __restrict__ X, float* __restrict__ out, int out_size) {
    const int tid = threadIdx.x;
    const int m0 = blockIdx.x * 128;
    const unsigned sb = (unsigned)__cvta_generic_to_shared(smem_raw);
    const int t128 = tid & 127;
    const int grp  = tid >> 7;             // == wx

    prefetch_ch(0, sb, t128, grp);

    // ---- prologue: read X fp32, split to fp16 hi/lo directly in smem ----
    {
        unsigned* xh = (unsigned*)smem_raw;             // row stride 132 u32
        unsigned* xl = (unsigned*)(smem_raw + XLO);
        #pragma unroll
        for (int i = 0; i < 32; i++) {
            int seg = tid + i * 256;        // 0..8191
            int row = seg >> 6, c4 = seg & 63;
            float4 xv = *(const float4*)&X[(m0 + row) * DIM + c4 * 4];
            unsigned lo01, lo23;
            unsigned hi01 = split2(xv.x * 32.0f, xv.y * 32.0f, &lo01);
            unsigned hi23 = split2(xv.z * 32.0f, xv.w * 32.0f, &lo23);
            xh[row * 132 + c4 * 2]     = hi01;
            xh[row * 132 + c4 * 2 + 1] = hi23;
            xl[row * 132 + c4 * 2]     = lo01;
            xl[row * 132 + c4 * 2 + 1] = lo23;
        }
    }
    __syncthreads();   // X slab visible to all; halves free-run from here

    const int lane = tid & 31;
    const int wid  = tid >> 5;
    const int wy   = wid & 3;       // m warp (0..3)
    const int wx   = wid >> 2;      // n warp (0..1) == grp
    const int gid  = lane >> 2;     // 0..7
    const int tq   = lane & 3;      // 0..3

    // LDSM per-lane bases
    const int arow = wy * 32 + (lane & 7) + ((lane >> 3) & 1) * 8;
    const unsigned a_hi0 = sb + XHI + (unsigned)arow * XS_ROW_BYTES + (unsigned)((lane >> 4) * 16);
    const unsigned a_hi1 = a_hi0 + 16u * XS_ROW_BYTES;
    const unsigned a_lo0 = a_hi0 + (XLO - XHI);
    const unsigned a_lo1 = a_lo0 + 16u * XS_ROW_BYTES;
    const int brow = wx * 64 + (lane & 7) + ((lane >> 4) & 1) * 8;
    const unsigned b_off = (unsigned)brow * CB_ROW_BYTES + (unsigned)(((lane >> 3) & 1) * 16);

    float bestv[4] = {3.4e38f, 3.4e38f, 3.4e38f, 3.4e38f};
    int   besti[4] = {0, 0, 0, 0};
    float acc[2][8][4];
    #pragma unroll
    for (int a = 0; a < 2; a++)
        #pragma unroll
        for (int b = 0; b < 8; b++)
            #pragma unroll
            for (int c = 0; c < 4; c++) acc[a][b][c] = 0.0f;

    for (int st = 0; st < 256; st++) {
        asm volatile("cp.async.wait_group 0;" ::: "memory");
        BARG(grp);
        if (st + 1 < 256) prefetch_ch(st + 1, sb, t128, grp);

        const unsigned bh_base = sb + SMEM_CB + (unsigned)(st & 1) * CB_BUF_BYTES + b_off;
        const unsigned bl_base = bh_base + CB_SPLIT_B;

        #pragma unroll
        for (int kk = 0; kk < 4; kk++) {
            const unsigned aoff = (unsigned)(((st & 3) * 64 + kk * 16) * 2);
            unsigned ahi[2][4], alo[2][4];
            LDSM_X4(ahi[0][0], ahi[0][1], ahi[0][2], ahi[0][3], a_hi0 + aoff);
            LDSM_X4(ahi[1][0], ahi[1][1], ahi[1][2], ahi[1][3], a_hi1 + aoff);
            LDSM_X4(alo[0][0], alo[0][1], alo[0][2], alo[0][3], a_lo0 + aoff);
            LDSM_X4(alo[1][0], alo[1][1], alo[1][2], alo[1][3], a_lo1 + aoff);
            #pragma unroll
            for (int p = 0; p < 4; p++) {
                unsigned bh0, bh1, bh2, bh3, bl0, bl1, bl2, bl3;
                LDSM_X4(bh0, bh1, bh2, bh3, bh_base + p * 2304u + kk * 32u);
                LDSM_X4(bl0, bl1, bl2, bl3, bl_base + p * 2304u + kk * 32u);
                #pragma unroll
                for (int ms = 0; ms < 2; ms++) {
                    MMA16816(acc[ms][2 * p],     ahi[ms], bh0, bh1);
                    MMA16816(acc[ms][2 * p],     ahi[ms], bl0, bl1);
                    MMA16816(acc[ms][2 * p],     alo[ms], bh0, bh1);
                    MMA16816(acc[ms][2 * p + 1], ahi[ms], bh2, bh3);
                    MMA16816(acc[ms][2 * p + 1], ahi[ms], bl2, bl3);
                    MMA16816(acc[ms][2 * p + 1], alo[ms], bh2, bh3);
                }
            }
        }

        if ((st & 3) == 3) {
            const int nt = st >> 2;
            #pragma unroll
            for (int nf = 0; nf < 8; nf++) {
                const int col = nt * 128 + wx * 64 + nf * 8 + tq * 2;
                const float cn0 = __ldg(&g_cnorm[col]);
                const float cn1 = __ldg(&g_cnorm[col + 1]);
                #pragma unroll
                for (int ms = 0; ms < 2; ms++) {
                    const int s0 = ms * 2, s1 = ms * 2 + 1;
                    float d0 = cn0 - acc[ms][nf][0] * INV2SCALE;
                    float d1 = cn1 - acc[ms][nf][1] * INV2SCALE;
                    float d2 = cn0 - acc[ms][nf][2] * INV2SCALE;
                    float d3 = cn1 - acc[ms][nf][3] * INV2SCALE;
                    if (d0 < bestv[s0]) { bestv[s0] = d0; besti[s0] = col; }
                    if (d1 < bestv[s0]) { bestv[s0] = d1; besti[s0] = col + 1; }
                    if (d2 < bestv[s1]) { bestv[s1] = d2; besti[s1] = col; }
                    if (d3 < bestv[s1]) { bestv[s1] = d3; besti[s1] = col + 1; }
                    acc[ms][nf][0] = 0.0f; acc[ms][nf][1] = 0.0f;
                    acc[ms][nf][2] = 0.0f; acc[ms][nf][3] = 0.0f;
                }
            }
        }
    }

    // ---- cross-thread reduce: 8 candidates per row ----
    float* rv   = (float*)(smem_raw + SMEM_RED);
    int*   ri   = (int*)(smem_raw + SMEM_RED + 4096);
    int*   sidx = (int*)(smem_raw + SMEM_RED + 8192);
    __syncthreads();
    #pragma unroll
    for (int s = 0; s < 4; s++) {
        // slot s = ms*2 + rowhalf covers row wy*32 + ms*16 + rowhalf*8 + gid
        const int row = wy * 32 + (s >> 1) * 16 + (s & 1) * 8 + gid;
        rv[row * 8 + wx * 4 + tq] = bestv[s];
        ri[row * 8 + wx * 4 + tq] = besti[s];
    }
    __syncthreads();
    if (tid < 128) {
        float bv = rv[tid * 8];
        int   bi = ri[tid * 8];
        #pragma unroll
        for (int j = 1; j < 8; j++) {
            float v = rv[tid * 8 + j];
            int  ii = ri[tid * 8 + j];
            if (v < bv || (v == bv && ii < bi)) { bv = v; bi = ii; }
        }
        g_idx[m0 + tid] = bi;
        sidx[tid] = bi;
        const int p = N_ROWS * DIM + 1 + m0 + tid;
        if (p < out_size) out[p] = (float)bi;
    }
    __syncthreads();

    // ---- fused gather + loss partials: thread t -> row t>>1, half columns ----
    {
        const int row = tid >> 1;
        const int cof = (tid & 1) * 128;    // float offset within row
        const int bi  = sidx[row];
        const float* cb = &g_codebook[bi * DIM + cof];
        const float* xr = &X[(m0 + row) * DIM + cof];
        float s = 0.0f;
        #pragma unroll
        for (int i = 0; i < 32; i++) {
            float4 c = *(const float4*)&cb[i * 4];
            float4 x = *(const float4*)&xr[i * 4];
            const int p = (m0 + row) * DIM + cof + i * 4;
            if (p + 3 < out_size) *(float4*)&out[p] = c;
            float dx = c.x - x.x, dy = c.y - x.y, dz = c.z - x.z, dw = c.w - x.w;
            s += dx * dx + dy * dy + dz * dz + dw * dw;
        }
        s += __shfl_xor_sync(0xffffffffu, s, 1);
        if ((tid & 1) == 0) g_partial[m0 + row] = s;
    }
}

// ---------------------------------------------------------------------------
__global__ void finalize_kernel(float* __restrict__ out, int out_size) {
    __shared__ float sm[1024];
    const int t = threadIdx.x;
    float s = 0.0f;
    for (int i = t; i < N_ROWS; i += 1024) s += g_partial[i];
    sm[t] = s;
    __syncthreads();
    for (int off = 512; off > 0; off >>= 1) {
        if (t < off) sm[t] += sm[t + off];
        __syncthreads();
    }
    if (t == 0) {
        const int p = N_ROWS * DIM;
        if (p < out_size)
            out[p] = sm[0] * (1.0f + BETA) / (float)(N_ROWS * DIM);
    }
}

// ---------------------------------------------------------------------------
extern "C" void kernel_launch(void* const* d_in, const int* in_sizes, int n_in,
                              void* d_out, int out_size) {
    const float* X = (const float*)d_in[0];
    const float* E = (const float*)d_in[1];
    const float* W = (const float*)d_in[2];
    const float* b = (const float*)d_in[3];
    float* out = (float*)d_out;

    cudaFuncSetAttribute(argmin_mma_kernel,
                         cudaFuncAttributeMaxDynamicSharedMemorySize,
                         SMEM_TOTAL_B);

    codebook_kernel<<<dim3(NEMB / 64, DIM / 64), 256>>>(E, W, b);
    cnorm_kernel<<<NEMB, 64>>>();
    argmin_mma_kernel<<<N_ROWS / 128, 256, SMEM_TOTAL_B>>>(X, out, out_size);
    finalize_kernel<<<1, 1024>>>(out, out_size);
}

// round 7
// speedup vs baseline: 5.8455x; 1.3777x over previous
#include <cuda_runtime.h>
#include <cuda_fp16.h>
#include <cstdint>

#define N_ROWS 16384
#define DIM    256
#define NEMB   8192
#define BETA   0.25f
#define INV2SCALE 0.000244140625f   // 2/8192 ; acc = 8192*(x.c)
#define MARGIN 0.5f                 // >> worst-case hi-only dist error (~0.05)

// ------------------------- device scratch (no allocs) ----------------------
__device__ float  g_codebook[NEMB * DIM];
__device__ float  g_cnorm[NEMB];
__device__ __half g_chi[NEMB * DIM];
__device__ int    g_idx[N_ROWS];
__device__ float  g_partial[N_ROWS / 128];

// ------------------------- smem layout for argmin_mma ----------------------
#define XHI           0            // 128 rows x 264 halfs (8-half pad) = 67584B
#define XS_ROW_BYTES  528
#define SMEM_CB       67584        // 4-ring x (128 x 72 halfs) = 73728
#define CB_BUF_BYTES  18432
#define CB_ROW_BYTES  144
#define SMEM_RV       141312       // 128*16 floats = 8192
#define SMEM_RI       149504       // 8192
#define SMEM_SIDX     157696       // 512
#define SMEM_PRED     158208       // 512
#define SMEM_TOTAL_B  158720

__device__ __forceinline__ void cp16(unsigned dst, const void* src) {
    asm volatile("cp.async.cg.shared.global [%0], [%1], 16;"
                 :: "r"(dst), "l"(src) : "memory");
}

#define MMA16816(d, a, b0, b1)                                              \
    asm volatile("mma.sync.aligned.m16n8k16.row.col.f32.f16.f16.f32 "       \
                 "{%0,%1,%2,%3}, {%4,%5,%6,%7}, {%8,%9}, {%0,%1,%2,%3};"    \
                 : "+f"(d[0]), "+f"(d[1]), "+f"(d[2]), "+f"(d[3])           \
                 : "r"(a[0]), "r"(a[1]), "r"(a[2]), "r"(a[3]),              \
                   "r"(b0), "r"(b1))

#define LDSM_X4(r0, r1, r2, r3, addr)                                       \
    asm volatile("ldmatrix.sync.aligned.m8n8.x4.shared.b16 "                \
                 "{%0,%1,%2,%3}, [%4];"                                     \
                 : "=r"(r0), "=r"(r1), "=r"(r2), "=r"(r3) : "r"(addr))

#define BARG(g) asm volatile("bar.sync %0, 128;" :: "r"((g) + 1) : "memory")

__device__ __forceinline__ unsigned pack2h(float a, float b) {
    __half ha = __float2half_rn(a), hb = __float2half_rn(b);
    return ((unsigned)__half_as_ushort(hb) << 16) | __half_as_ushort(ha);
}

// ---------------------------------------------------------------------------
// Kernel A: codebook C[k][j] = sum_d E[k][d]*W[j][d] + b[j]  (exact fp32)
// epilogue also emits the scaled fp16 codebook (g_chi).
// ---------------------------------------------------------------------------
__global__ void codebook_kernel(const float* __restrict__ E,
                                const float* __restrict__ W,
                                const float* __restrict__ bias) {
    __shared__ __align__(16) float et[16][68];
    __shared__ __align__(16) float wt[16][68];
    const int tx = threadIdx.x & 15;
    const int ty = threadIdx.x >> 4;
    const int k0 = blockIdx.x * 64;
    const int j0 = blockIdx.y * 64;
    const int lr = threadIdx.x >> 2;
    const int lq = threadIdx.x & 3;

    float acc[4][4] = {};
    for (int dc = 0; dc < DIM; dc += 16) {
        float4 ev = *(const float4*)&E[(k0 + lr) * DIM + dc + lq * 4];
        float4 wv = *(const float4*)&W[(j0 + lr) * DIM + dc + lq * 4];
        et[lq * 4 + 0][lr] = ev.x; et[lq * 4 + 1][lr] = ev.y;
        et[lq * 4 + 2][lr] = ev.z; et[lq * 4 + 3][lr] = ev.w;
        wt[lq * 4 + 0][lr] = wv.x; wt[lq * 4 + 1][lr] = wv.y;
        wt[lq * 4 + 2][lr] = wv.z; wt[lq * 4 + 3][lr] = wv.w;
        __syncthreads();
        #pragma unroll
        for (int d = 0; d < 16; d++) {
            float4 a = *(const float4*)&et[d][ty * 4];
            float4 b = *(const float4*)&wt[d][tx * 4];
            acc[0][0] += a.x * b.x; acc[0][1] += a.x * b.y; acc[0][2] += a.x * b.z; acc[0][3] += a.x * b.w;
            acc[1][0] += a.y * b.x; acc[1][1] += a.y * b.y; acc[1][2] += a.y * b.z; acc[1][3] += a.y * b.w;
            acc[2][0] += a.z * b.x; acc[2][1] += a.z * b.y; acc[2][2] += a.z * b.z; acc[2][3] += a.z * b.w;
            acc[3][0] += a.w * b.x; acc[3][1] += a.w * b.y; acc[3][2] += a.w * b.z; acc[3][3] += a.w * b.w;
        }
        __syncthreads();
    }
    const float b0 = bias[j0 + tx * 4 + 0];
    const float b1 = bias[j0 + tx * 4 + 1];
    const float b2 = bias[j0 + tx * 4 + 2];
    const float b3 = bias[j0 + tx * 4 + 3];
    #pragma unroll
    for (int i = 0; i < 4; i++) {
        float4 v;
        v.x = acc[i][0] + b0; v.y = acc[i][1] + b1;
        v.z = acc[i][2] + b2; v.w = acc[i][3] + b3;
        const int k = k0 + ty * 4 + i;
        const int j = j0 + tx * 4;
        *(float4*)&g_codebook[k * DIM + j] = v;
        *(uint2*)&g_chi[k * DIM + j] =
            make_uint2(pack2h(v.x * 256.0f, v.y * 256.0f),
                       pack2h(v.z * 256.0f, v.w * 256.0f));
    }
}

// ---------------------------------------------------------------------------
__global__ void cnorm_kernel() {
    const int k = blockIdx.x;
    const int t = threadIdx.x;
    float4 c = *(const float4*)&g_codebook[k * DIM + t * 4];
    float s = c.x * c.x + c.y * c.y + c.z * c.z + c.w * c.w;
    #pragma unroll
    for (int off = 16; off > 0; off >>= 1)
        s += __shfl_down_sync(0xffffffffu, s, off);
    __shared__ float sm[2];
    if ((t & 31) == 0) sm[t >> 5] = s;
    __syncthreads();
    if (t == 0) g_cnorm[k] = sm[0] + sm[1];
}

// ---------------------------------------------------------------------------
// Kernel B: hi-only fp16 mma.sync distance GEMM (candidate pass) + exact fp32
// refinement + fused gather/loss. 128 blocks x 256 threads, two independent
// 128-thread halves (named barriers). 4-deep cp.async ring (prefetch 3 ahead).
// ---------------------------------------------------------------------------
extern __shared__ char smem_raw[];

__device__ __forceinline__ void prefetch_ch(int st, unsigned sbase, int t128, int g) {
    const int nt = st >> 2;
    const int ks = st & 3;
    const __half* src = g_chi + (nt * 128 + g * 64) * DIM + ks * 64;
    const unsigned db = sbase + SMEM_CB + (unsigned)(st & 3) * CB_BUF_BYTES
                      + (unsigned)g * 64u * CB_ROW_BYTES;
    #pragma unroll
    for (int i = 0; i < 4; i++) {
        int seg = t128 + i * 128;       // 0..511 : 64 rows x 8 parts
        int row = seg >> 3, part = seg & 7;
        cp16(db + row * CB_ROW_BYTES + part * 16, src + row * DIM + part * 8);
    }
    asm volatile("cp.async.commit_group;" ::: "memory");
}

__global__ void __launch_bounds__(256, 1) argmin_mma_kernel(
        const float* __restrict__ X, float* __restrict__ out, int out_size) {
    const int tid = threadIdx.x;
    const int m0 = blockIdx.x * 128;
    const unsigned sb = (unsigned)__cvta_generic_to_shared(smem_raw);
    const int t128 = tid & 127;
    const int grp  = tid >> 7;             // == wx

    prefetch_ch(0, sb, t128, grp);
    prefetch_ch(1, sb, t128, grp);
    prefetch_ch(2, sb, t128, grp);

    // ---- prologue: read X fp32, convert fp16 hi into smem ----
    {
        unsigned* xh = (unsigned*)smem_raw;             // row stride 132 u32
        #pragma unroll
        for (int i = 0; i < 32; i++) {
            int seg = tid + i * 256;        // 0..8191
            int row = seg >> 6, c4 = seg & 63;
            float4 xv = *(const float4*)&X[(m0 + row) * DIM + c4 * 4];
            xh[row * 132 + c4 * 2]     = pack2h(xv.x * 32.0f, xv.y * 32.0f);
            xh[row * 132 + c4 * 2 + 1] = pack2h(xv.z * 32.0f, xv.w * 32.0f);
        }
    }
    __syncthreads();   // X slab visible; halves free-run from here

    const int lane = tid & 31;
    const int wid  = tid >> 5;
    const int wy   = wid & 3;       // m warp (0..3)
    const int wx   = wid >> 2;      // n warp (0..1) == grp
    const int gid  = lane >> 2;     // 0..7
    const int tq   = lane & 3;      // 0..3

    const int arow = wy * 32 + (lane & 7) + ((lane >> 3) & 1) * 8;
    const unsigned a_hi0 = sb + XHI + (unsigned)arow * XS_ROW_BYTES + (unsigned)((lane >> 4) * 16);
    const unsigned a_hi1 = a_hi0 + 16u * XS_ROW_BYTES;
    const int brow = wx * 64 + (lane & 7) + ((lane >> 4) & 1) * 8;
    const unsigned b_off = (unsigned)brow * CB_ROW_BYTES + (unsigned)(((lane >> 3) & 1) * 16);

    // best-2 per row-slot (4 slots)
    float bv1[4] = {3.4e38f, 3.4e38f, 3.4e38f, 3.4e38f};
    float bv2[4] = {3.4e38f, 3.4e38f, 3.4e38f, 3.4e38f};
    int   bi1[4] = {0, 0, 0, 0};
    int   bi2[4] = {0, 0, 0, 0};
    float acc[2][8][4];
    #pragma unroll
    for (int a = 0; a < 2; a++)
        #pragma unroll
        for (int b = 0; b < 8; b++)
            #pragma unroll
            for (int c = 0; c < 4; c++) acc[a][b][c] = 0.0f;

    for (int st = 0; st < 256; st++) {
        asm volatile("cp.async.wait_group 2;" ::: "memory");
        BARG(grp);
        if (st + 3 < 256) prefetch_ch(st + 3, sb, t128, grp);
        else asm volatile("cp.async.commit_group;" ::: "memory");

        const unsigned bh_base = sb + SMEM_CB + (unsigned)(st & 3) * CB_BUF_BYTES + b_off;

        #pragma unroll
        for (int kk = 0; kk < 4; kk++) {
            const unsigned aoff = (unsigned)(((st & 3) * 64 + kk * 16) * 2);
            unsigned ahi[2][4];
            LDSM_X4(ahi[0][0], ahi[0][1], ahi[0][2], ahi[0][3], a_hi0 + aoff);
            LDSM_X4(ahi[1][0], ahi[1][1], ahi[1][2], ahi[1][3], a_hi1 + aoff);
            #pragma unroll
            for (int p = 0; p < 4; p++) {
                unsigned bh0, bh1, bh2, bh3;
                LDSM_X4(bh0, bh1, bh2, bh3, bh_base + p * 2304u + kk * 32u);
                #pragma unroll
                for (int ms = 0; ms < 2; ms++) {
                    MMA16816(acc[ms][2 * p],     ahi[ms], bh0, bh1);
                    MMA16816(acc[ms][2 * p + 1], ahi[ms], bh2, bh3);
                }
            }
        }

        if ((st & 3) == 3) {
            const int nt = st >> 2;
            #pragma unroll
            for (int nf = 0; nf < 8; nf++) {
                const int col = nt * 128 + wx * 64 + nf * 8 + tq * 2;
                const float cn0 = __ldg(&g_cnorm[col]);
                const float cn1 = __ldg(&g_cnorm[col + 1]);
                #pragma unroll
                for (int ms = 0; ms < 2; ms++) {
                    const int s0 = ms * 2, s1 = ms * 2 + 1;
                    float d0 = cn0 - acc[ms][nf][0] * INV2SCALE;
                    float d1 = cn1 - acc[ms][nf][1] * INV2SCALE;
                    float d2 = cn0 - acc[ms][nf][2] * INV2SCALE;
                    float d3 = cn1 - acc[ms][nf][3] * INV2SCALE;
                    if (d0 < bv1[s0]) { bv2[s0]=bv1[s0]; bi2[s0]=bi1[s0]; bv1[s0]=d0; bi1[s0]=col; }
                    else if (d0 < bv2[s0]) { bv2[s0]=d0; bi2[s0]=col; }
                    if (d1 < bv1[s0]) { bv2[s0]=bv1[s0]; bi2[s0]=bi1[s0]; bv1[s0]=d1; bi1[s0]=col+1; }
                    else if (d1 < bv2[s0]) { bv2[s0]=d1; bi2[s0]=col+1; }
                    if (d2 < bv1[s1]) { bv2[s1]=bv1[s1]; bi2[s1]=bi1[s1]; bv1[s1]=d2; bi1[s1]=col; }
                    else if (d2 < bv2[s1]) { bv2[s1]=d2; bi2[s1]=col; }
                    if (d3 < bv1[s1]) { bv2[s1]=bv1[s1]; bi2[s1]=bi1[s1]; bv1[s1]=d3; bi1[s1]=col+1; }
                    else if (d3 < bv2[s1]) { bv2[s1]=d3; bi2[s1]=col+1; }
                    acc[ms][nf][0] = 0.0f; acc[ms][nf][1] = 0.0f;
                    acc[ms][nf][2] = 0.0f; acc[ms][nf][3] = 0.0f;
                }
            }
        }
    }

    // ---- stage 16 candidates/row, refine with exact fp32 distances ----
    float* rv   = (float*)(smem_raw + SMEM_RV);
    int*   ri   = (int*)(smem_raw + SMEM_RI);
    int*   sidx = (int*)(smem_raw + SMEM_SIDX);
    float* pred = (float*)(smem_raw + SMEM_PRED);
    __syncthreads();
    #pragma unroll
    for (int s = 0; s < 4; s++) {
        const int row = wy * 32 + (s >> 1) * 16 + (s & 1) * 8 + gid;
        const int base = row * 16 + (wx * 4 + tq) * 2;
        rv[base] = bv1[s];  ri[base] = bi1[s];
        rv[base + 1] = bv2[s];  ri[base + 1] = bi2[s];
    }
    __syncthreads();
    if (tid < 128) {
        const int row = tid;
        float bv = rv[row * 16];
        #pragma unroll
        for (int j = 1; j < 16; j++) bv = fminf(bv, rv[row * 16 + j]);
        const float thresh = bv + MARGIN;
        const float* xr = &X[(m0 + row) * DIM];
        float bestd = 3.4e38f;
        int   besti = NEMB;
        for (int j = 0; j < 16; j++) {
            float v = rv[row * 16 + j];
            if (v <= thresh) {
                const int k = ri[row * 16 + j];
                const float* cb = &g_codebook[k * DIM];
                float dot = 0.0f;
                #pragma unroll 8
                for (int i = 0; i < 64; i++) {
                    float4 c = *(const float4*)&cb[i * 4];
                    float4 x = *(const float4*)&xr[i * 4];
                    dot += c.x * x.x + c.y * x.y + c.z * x.z + c.w * x.w;
                }
                float d = __ldg(&g_cnorm[k]) - 2.0f * dot;
                if (d < bestd || (d == bestd && k < besti)) { bestd = d; besti = k; }
            }
        }
        g_idx[m0 + row] = besti;
        sidx[row] = besti;
        const int p = N_ROWS * DIM + 1 + m0 + row;
        if (p < out_size) out[p] = (float)besti;
    }
    __syncthreads();

    // ---- fused gather + loss partial: thread t -> row t>>1, half columns ----
    {
        const int row = tid >> 1;
        const int cof = (tid & 1) * 128;
        const int bi  = sidx[row];
        const float* cb = &g_codebook[bi * DIM + cof];
        const float* xr = &X[(m0 + row) * DIM + cof];
        float s = 0.0f;
        #pragma unroll
        for (int i = 0; i < 32; i++) {
            float4 c = *(const float4*)&cb[i * 4];
            float4 x = *(const float4*)&xr[i * 4];
            const int p = (m0 + row) * DIM + cof + i * 4;
            if (p + 3 < out_size) *(float4*)&out[p] = c;
            float dx = c.x - x.x, dy = c.y - x.y, dz = c.z - x.z, dw = c.w - x.w;
            s += dx * dx + dy * dy + dz * dz + dw * dw;
        }
        s += __shfl_xor_sync(0xffffffffu, s, 1);
        if ((tid & 1) == 0) pred[row] = s;
    }
    __syncthreads();
    // per-CTA reduction of 128 row partials (deterministic tree)
    if (tid < 64) pred[tid] += pred[tid + 64];
    __syncthreads();
    if (tid < 32) {
        float s = pred[tid] + pred[tid + 32];
        #pragma unroll
        for (int off = 16; off > 0; off >>= 1)
            s += __shfl_down_sync(0xffffffffu, s, off);
        if (tid == 0) g_partial[blockIdx.x] = s;
    }
}

// ---------------------------------------------------------------------------
__global__ void finalize_kernel(float* __restrict__ out, int out_size) {
    __shared__ float sm[128];
    const int t = threadIdx.x;
    sm[t] = g_partial[t];
    __syncthreads();
    if (t < 64) sm[t] += sm[t + 64];
    __syncthreads();
    if (t < 32) {
        float s = sm[t] + sm[t + 32];
        #pragma unroll
        for (int off = 16; off > 0; off >>= 1)
            s += __shfl_down_sync(0xffffffffu, s, off);
        if (t == 0) {
            const int p = N_ROWS * DIM;
            if (p < out_size)
                out[p] = s * (1.0f + BETA) / (float)(N_ROWS * DIM);
        }
    }
}

// ---------------------------------------------------------------------------
extern "C" void kernel_launch(void* const* d_in, const int* in_sizes, int n_in,
                              void* d_out, int out_size) {
    const float* X = (const float*)d_in[0];
    const float* E = (const float*)d_in[1];
    const float* W = (const float*)d_in[2];
    const float* b = (const float*)d_in[3];
    float* out = (float*)d_out;

    cudaFuncSetAttribute(argmin_mma_kernel,
                         cudaFuncAttributeMaxDynamicSharedMemorySize,
                         SMEM_TOTAL_B);

    codebook_kernel<<<dim3(NEMB / 64, DIM / 64), 256>>>(E, W, b);
    cnorm_kernel<<<NEMB, 64>>>();
    argmin_mma_kernel<<<N_ROWS / 128, 256, SMEM_TOTAL_B>>>(X, out, out_size);
    finalize_kernel<<<1, 128>>>(out, out_size);
}

// round 8
// speedup vs baseline: 6.9041x; 1.1811x over previous
#include <cuda_runtime.h>
#include <cuda_fp16.h>
#include <cstdint>

#define N_ROWS 16384
#define DIM    256
#define NEMB   8192
#define BETA   0.25f
#define INV2SCALE 0.000244140625f   // 2/8192 ; acc = 8192*(x.c)
#define MARGIN 0.5f                 // >> worst-case hi-only dist error (~0.05)

// ------------------------- device scratch (no allocs) ----------------------
__device__ float  g_codebook[NEMB * DIM];
__device__ float  g_cnorm[NEMB];
__device__ __half g_chi[NEMB * DIM];
__device__ int    g_idx[N_ROWS];
__device__ float  g_partial[N_ROWS / 128];

// ------------------------- smem layout for argmin_mma ----------------------
#define XHI           0            // 128 rows x 264 halfs (8-half pad) = 67584B
#define XS_ROW_BYTES  528
#define SMEM_CB       67584        // 4-ring x (128 x 72 halfs) = 73728
#define CB_BUF_BYTES  18432
#define CB_ROW_BYTES  144
#define SMEM_RV       141312       // 128*32 floats = 16384
#define SMEM_RI       157696       // 16384
#define SMEM_SIDX     174080       // 512
#define SMEM_PRED     174592       // 512
#define SMEM_TOTAL_B  175104

__device__ __forceinline__ void cp16(unsigned dst, const void* src) {
    asm volatile("cp.async.cg.shared.global [%0], [%1], 16;"
                 :: "r"(dst), "l"(src) : "memory");
}

#define MMA16816(d, a, b0, b1)                                              \
    asm volatile("mma.sync.aligned.m16n8k16.row.col.f32.f16.f16.f32 "       \
                 "{%0,%1,%2,%3}, {%4,%5,%6,%7}, {%8,%9}, {%0,%1,%2,%3};"    \
                 : "+f"(d[0]), "+f"(d[1]), "+f"(d[2]), "+f"(d[3])           \
                 : "r"(a[0]), "r"(a[1]), "r"(a[2]), "r"(a[3]),              \
                   "r"(b0), "r"(b1))

#define LDSM_X4(r0, r1, r2, r3, addr)                                       \
    asm volatile("ldmatrix.sync.aligned.m8n8.x4.shared.b16 "                \
                 "{%0,%1,%2,%3}, [%4];"                                     \
                 : "=r"(r0), "=r"(r1), "=r"(r2), "=r"(r3) : "r"(addr))

#define BARG(g) asm volatile("bar.sync %0, 128;" :: "r"((g) + 1) : "memory")

__device__ __forceinline__ unsigned pack2h(float a, float b) {
    __half ha = __float2half_rn(a), hb = __float2half_rn(b);
    return ((unsigned)__half_as_ushort(hb) << 16) | __half_as_ushort(ha);
}

// ---------------------------------------------------------------------------
// Kernel A: codebook C[k][j] = sum_d E[k][d]*W[j][d] + b[j]  (exact fp32)
// epilogue also emits the scaled fp16 codebook (g_chi).
// ---------------------------------------------------------------------------
__global__ void codebook_kernel(const float* __restrict__ E,
                                const float* __restrict__ W,
                                const float* __restrict__ bias) {
    __shared__ __align__(16) float et[16][68];
    __shared__ __align__(16) float wt[16][68];
    const int tx = threadIdx.x & 15;
    const int ty = threadIdx.x >> 4;
    const int k0 = blockIdx.x * 64;
    const int j0 = blockIdx.y * 64;
    const int lr = threadIdx.x >> 2;
    const int lq = threadIdx.x & 3;

    float acc[4][4] = {};
    for (int dc = 0; dc < DIM; dc += 16) {
        float4 ev = *(const float4*)&E[(k0 + lr) * DIM + dc + lq * 4];
        float4 wv = *(const float4*)&W[(j0 + lr) * DIM + dc + lq * 4];
        et[lq * 4 + 0][lr] = ev.x; et[lq * 4 + 1][lr] = ev.y;
        et[lq * 4 + 2][lr] = ev.z; et[lq * 4 + 3][lr] = ev.w;
        wt[lq * 4 + 0][lr] = wv.x; wt[lq * 4 + 1][lr] = wv.y;
        wt[lq * 4 + 2][lr] = wv.z; wt[lq * 4 + 3][lr] = wv.w;
        __syncthreads();
        #pragma unroll
        for (int d = 0; d < 16; d++) {
            float4 a = *(const float4*)&et[d][ty * 4];
            float4 b = *(const float4*)&wt[d][tx * 4];
            acc[0][0] += a.x * b.x; acc[0][1] += a.x * b.y; acc[0][2] += a.x * b.z; acc[0][3] += a.x * b.w;
            acc[1][0] += a.y * b.x; acc[1][1] += a.y * b.y; acc[1][2] += a.y * b.z; acc[1][3] += a.y * b.w;
            acc[2][0] += a.z * b.x; acc[2][1] += a.z * b.y; acc[2][2] += a.z * b.z; acc[2][3] += a.z * b.w;
            acc[3][0] += a.w * b.x; acc[3][1] += a.w * b.y; acc[3][2] += a.w * b.z; acc[3][3] += a.w * b.w;
        }
        __syncthreads();
    }
    const float b0 = bias[j0 + tx * 4 + 0];
    const float b1 = bias[j0 + tx * 4 + 1];
    const float b2 = bias[j0 + tx * 4 + 2];
    const float b3 = bias[j0 + tx * 4 + 3];
    #pragma unroll
    for (int i = 0; i < 4; i++) {
        float4 v;
        v.x = acc[i][0] + b0; v.y = acc[i][1] + b1;
        v.z = acc[i][2] + b2; v.w = acc[i][3] + b3;
        const int k = k0 + ty * 4 + i;
        const int j = j0 + tx * 4;
        *(float4*)&g_codebook[k * DIM + j] = v;
        *(uint2*)&g_chi[k * DIM + j] =
            make_uint2(pack2h(v.x * 256.0f, v.y * 256.0f),
                       pack2h(v.z * 256.0f, v.w * 256.0f));
    }
}

// ---------------------------------------------------------------------------
__global__ void cnorm_kernel() {
    const int k = blockIdx.x;
    const int t = threadIdx.x;
    float4 c = *(const float4*)&g_codebook[k * DIM + t * 4];
    float s = c.x * c.x + c.y * c.y + c.z * c.z + c.w * c.w;
    #pragma unroll
    for (int off = 16; off > 0; off >>= 1)
        s += __shfl_down_sync(0xffffffffu, s, off);
    __shared__ float sm[2];
    if ((t & 31) == 0) sm[t >> 5] = s;
    __syncthreads();
    if (t == 0) g_cnorm[k] = sm[0] + sm[1];
}

// ---------------------------------------------------------------------------
// Kernel B: hi-only fp16 mma.sync candidate GEMM + exact fp32 refinement +
// fused gather/loss. 128 blocks x 512 threads: 4(m) x 4(n) warps, warp tile
// 32x32. Four independent 128-thread quarters (named barriers), each owns
// 32 B-rows. 4-deep cp.async ring (prefetch 3 ahead).
// ---------------------------------------------------------------------------
extern __shared__ char smem_raw[];

__device__ __forceinline__ void prefetch_ch(int st, unsigned sbase, int t128, int g) {
    const int nt = st >> 2;
    const int ks = st & 3;
    const __half* src = g_chi + (nt * 128 + g * 32) * DIM + ks * 64;
    const unsigned db = sbase + SMEM_CB + (unsigned)(st & 3) * CB_BUF_BYTES
                      + (unsigned)g * 32u * CB_ROW_BYTES;
    #pragma unroll
    for (int i = 0; i < 2; i++) {
        int seg = t128 + i * 128;       // 0..255 : 32 rows x 8 parts
        int row = seg >> 3, part = seg & 7;
        cp16(db + row * CB_ROW_BYTES + part * 16, src + row * DIM + part * 8);
    }
    asm volatile("cp.async.commit_group;" ::: "memory");
}

__global__ void __launch_bounds__(512, 1) argmin_mma_kernel(
        const float* __restrict__ X, float* __restrict__ out, int out_size) {
    const int tid = threadIdx.x;
    const int m0 = blockIdx.x * 128;
    const unsigned sb = (unsigned)__cvta_generic_to_shared(smem_raw);
    const int t128 = tid & 127;
    const int grp  = tid >> 7;             // == wx (0..3)

    prefetch_ch(0, sb, t128, grp);
    prefetch_ch(1, sb, t128, grp);
    prefetch_ch(2, sb, t128, grp);

    // ---- prologue: read X fp32, convert fp16 hi into smem ----
    {
        unsigned* xh = (unsigned*)smem_raw;             // row stride 132 u32
        #pragma unroll
        for (int i = 0; i < 16; i++) {
            int seg = tid + i * 512;        // 0..8191
            int row = seg >> 6, c4 = seg & 63;
            float4 xv = *(const float4*)&X[(m0 + row) * DIM + c4 * 4];
            xh[row * 132 + c4 * 2]     = pack2h(xv.x * 32.0f, xv.y * 32.0f);
            xh[row * 132 + c4 * 2 + 1] = pack2h(xv.z * 32.0f, xv.w * 32.0f);
        }
    }
    __syncthreads();   // X slab visible; quarters free-run from here

    const int lane = tid & 31;
    const int wid  = tid >> 5;
    const int wy   = wid & 3;       // m warp (0..3)
    const int wx   = wid >> 2;      // n warp (0..3) == grp
    const int gid  = lane >> 2;     // 0..7
    const int tq   = lane & 3;      // 0..3

    const int arow = wy * 32 + (lane & 7) + ((lane >> 3) & 1) * 8;
    const unsigned a_hi0 = sb + XHI + (unsigned)arow * XS_ROW_BYTES + (unsigned)((lane >> 4) * 16);
    const unsigned a_hi1 = a_hi0 + 16u * XS_ROW_BYTES;
    const int brow = wx * 32 + (lane & 7) + ((lane >> 4) & 1) * 8;
    const unsigned b_off = (unsigned)brow * CB_ROW_BYTES + (unsigned)(((lane >> 3) & 1) * 16);

    // best-2 per row-slot (4 slots: ms x rowhalf)
    float bv1[4] = {3.4e38f, 3.4e38f, 3.4e38f, 3.4e38f};
    float bv2[4] = {3.4e38f, 3.4e38f, 3.4e38f, 3.4e38f};
    int   bi1[4] = {0, 0, 0, 0};
    int   bi2[4] = {0, 0, 0, 0};
    float acc[2][4][4];
    #pragma unroll
    for (int a = 0; a < 2; a++)
        #pragma unroll
        for (int b = 0; b < 4; b++)
            #pragma unroll
            for (int c = 0; c < 4; c++) acc[a][b][c] = 0.0f;

    for (int st = 0; st < 256; st++) {
        asm volatile("cp.async.wait_group 2;" ::: "memory");
        BARG(grp);
        if (st + 3 < 256) prefetch_ch(st + 3, sb, t128, grp);
        else asm volatile("cp.async.commit_group;" ::: "memory");

        const unsigned bh_base = sb + SMEM_CB + (unsigned)(st & 3) * CB_BUF_BYTES + b_off;

        #pragma unroll
        for (int kk = 0; kk < 4; kk++) {
            const unsigned aoff = (unsigned)(((st & 3) * 64 + kk * 16) * 2);
            unsigned ahi[2][4];
            LDSM_X4(ahi[0][0], ahi[0][1], ahi[0][2], ahi[0][3], a_hi0 + aoff);
            LDSM_X4(ahi[1][0], ahi[1][1], ahi[1][2], ahi[1][3], a_hi1 + aoff);
            #pragma unroll
            for (int p = 0; p < 2; p++) {
                unsigned bh0, bh1, bh2, bh3;
                LDSM_X4(bh0, bh1, bh2, bh3, bh_base + p * 2304u + kk * 32u);
                #pragma unroll
                for (int ms = 0; ms < 2; ms++) {
                    MMA16816(acc[ms][2 * p],     ahi[ms], bh0, bh1);
                    MMA16816(acc[ms][2 * p + 1], ahi[ms], bh2, bh3);
                }
            }
        }

        if ((st & 3) == 3) {
            const int nt = st >> 2;
            #pragma unroll
            for (int nf = 0; nf < 4; nf++) {
                const int col = nt * 128 + wx * 32 + nf * 8 + tq * 2;
                const float cn0 = __ldg(&g_cnorm[col]);
                const float cn1 = __ldg(&g_cnorm[col + 1]);
                #pragma unroll
                for (int ms = 0; ms < 2; ms++) {
                    const int s0 = ms * 2, s1 = ms * 2 + 1;
                    float d0 = cn0 - acc[ms][nf][0] * INV2SCALE;
                    float d1 = cn1 - acc[ms][nf][1] * INV2SCALE;
                    float d2 = cn0 - acc[ms][nf][2] * INV2SCALE;
                    float d3 = cn1 - acc[ms][nf][3] * INV2SCALE;
                    if (d0 < bv1[s0]) { bv2[s0]=bv1[s0]; bi2[s0]=bi1[s0]; bv1[s0]=d0; bi1[s0]=col; }
                    else if (d0 < bv2[s0]) { bv2[s0]=d0; bi2[s0]=col; }
                    if (d1 < bv1[s0]) { bv2[s0]=bv1[s0]; bi2[s0]=bi1[s0]; bv1[s0]=d1; bi1[s0]=col+1; }
                    else if (d1 < bv2[s0]) { bv2[s0]=d1; bi2[s0]=col+1; }
                    if (d2 < bv1[s1]) { bv2[s1]=bv1[s1]; bi2[s1]=bi1[s1]; bv1[s1]=d2; bi1[s1]=col; }
                    else if (d2 < bv2[s1]) { bv2[s1]=d2; bi2[s1]=col; }
                    if (d3 < bv1[s1]) { bv2[s1]=bv1[s1]; bi2[s1]=bi1[s1]; bv1[s1]=d3; bi1[s1]=col+1; }
                    else if (d3 < bv2[s1]) { bv2[s1]=d3; bi2[s1]=col+1; }
                    acc[ms][nf][0] = 0.0f; acc[ms][nf][1] = 0.0f;
                    acc[ms][nf][2] = 0.0f; acc[ms][nf][3] = 0.0f;
                }
            }
        }
    }

    // ---- stage 32 candidates/row, refine with exact fp32 distances ----
    float* rv   = (float*)(smem_raw + SMEM_RV);
    int*   ri   = (int*)(smem_raw + SMEM_RI);
    int*   sidx = (int*)(smem_raw + SMEM_SIDX);
    float* pred = (float*)(smem_raw + SMEM_PRED);
    __syncthreads();
    #pragma unroll
    for (int s = 0; s < 4; s++) {
        const int row = wy * 32 + (s >> 1) * 16 + (s & 1) * 8 + gid;
        const int base = row * 32 + (wx * 4 + tq) * 2;
        rv[base] = bv1[s];  ri[base] = bi1[s];
        rv[base + 1] = bv2[s];  ri[base + 1] = bi2[s];
    }
    __syncthreads();
    if (tid < 128) {
        const int row = tid;
        float bv = rv[row * 32];
        #pragma unroll
        for (int j = 1; j < 32; j++) bv = fminf(bv, rv[row * 32 + j]);
        const float thresh = bv + MARGIN;
        const float* xr = &X[(m0 + row) * DIM];
        float bestd = 3.4e38f;
        int   besti = NEMB;
        for (int j = 0; j < 32; j++) {
            float v = rv[row * 32 + j];
            if (v <= thresh) {
                const int k = ri[row * 32 + j];
                const float* cb = &g_codebook[k * DIM];
                float dot = 0.0f;
                #pragma unroll 8
                for (int i = 0; i < 64; i++) {
                    float4 c = *(const float4*)&cb[i * 4];
                    float4 x = *(const float4*)&xr[i * 4];
                    dot += c.x * x.x + c.y * x.y + c.z * x.z + c.w * x.w;
                }
                float d = __ldg(&g_cnorm[k]) - 2.0f * dot;
                if (d < bestd || (d == bestd && k < besti)) { bestd = d; besti = k; }
            }
        }
        g_idx[m0 + row] = besti;
        sidx[row] = besti;
        const int p = N_ROWS * DIM + 1 + m0 + row;
        if (p < out_size) out[p] = (float)besti;
    }
    __syncthreads();

    // ---- fused gather + loss partial: thread t -> row t>>2, quarter row ----
    {
        const int row = tid >> 2;
        const int cof = (tid & 3) * 64;
        const int bi  = sidx[row];
        const float* cb = &g_codebook[bi * DIM + cof];
        const float* xr = &X[(m0 + row) * DIM + cof];
        float s = 0.0f;
        #pragma unroll
        for (int i = 0; i < 16; i++) {
            float4 c = *(const float4*)&cb[i * 4];
            float4 x = *(const float4*)&xr[i * 4];
            const int p = (m0 + row) * DIM + cof + i * 4;
            if (p + 3 < out_size) *(float4*)&out[p] = c;
            float dx = c.x - x.x, dy = c.y - x.y, dz = c.z - x.z, dw = c.w - x.w;
            s += dx * dx + dy * dy + dz * dz + dw * dw;
        }
        s += __shfl_xor_sync(0xffffffffu, s, 1);
        s += __shfl_xor_sync(0xffffffffu, s, 2);
        if ((tid & 3) == 0) pred[row] = s;
    }
    __syncthreads();
    // per-CTA reduction of 128 row partials (deterministic tree)
    if (tid < 64) pred[tid] += pred[tid + 64];
    __syncthreads();
    if (tid < 32) {
        float s = pred[tid] + pred[tid + 32];
        #pragma unroll
        for (int off = 16; off > 0; off >>= 1)
            s += __shfl_down_sync(0xffffffffu, s, off);
        if (tid == 0) g_partial[blockIdx.x] = s;
    }
}

// ---------------------------------------------------------------------------
__global__ void finalize_kernel(float* __restrict__ out, int out_size) {
    __shared__ float sm[128];
    const int t = threadIdx.x;
    sm[t] = g_partial[t];
    __syncthreads();
    if (t < 64) sm[t] += sm[t + 64];
    __syncthreads();
    if (t < 32) {
        float s = sm[t] + sm[t + 32];
        #pragma unroll
        for (int off = 16; off > 0; off >>= 1)
            s += __shfl_down_sync(0xffffffffu, s, off);
        if (t == 0) {
            const int p = N_ROWS * DIM;
            if (p < out_size)
                out[p] = s * (1.0f + BETA) / (float)(N_ROWS * DIM);
        }
    }
}

// ---------------------------------------------------------------------------
extern "C" void kernel_launch(void* const* d_in, const int* in_sizes, int n_in,
                              void* d_out, int out_size) {
    const float* X = (const float*)d_in[0];
    const float* E = (const float*)d_in[1];
    const float* W = (const float*)d_in[2];
    const float* b = (const float*)d_in[3];
    float* out = (float*)d_out;

    cudaFuncSetAttribute(argmin_mma_kernel,
                         cudaFuncAttributeMaxDynamicSharedMemorySize,
                         SMEM_TOTAL_B);

    codebook_kernel<<<dim3(NEMB / 64, DIM / 64), 256>>>(E, W, b);
    cnorm_kernel<<<NEMB, 64>>>();
    argmin_mma_kernel<<<N_ROWS / 128, 512, SMEM_TOTAL_B>>>(X, out, out_size);
    finalize_kernel<<<1, 128>>>(out, out_size);
}